// round 1
// baseline (speedup 1.0000x reference)
#include <cuda_runtime.h>
#include <math.h>

#define BB     4
#define SS     2048
#define DMODEL 1024
#define NH     16
#define HD     64
#define HDIM   1024   // NH*HD
#define RK     8
#define TOK    (BB*SS)   // 8192

// ------------------- device scratch (static; allocation-free) -------------------
__device__ float g_Weq[DMODEL*HDIM];
__device__ float g_Wek[DMODEL*HDIM];
__device__ float g_WvL[DMODEL*HDIM];
__device__ float g_beq[HDIM];
__device__ float g_bek[HDIM];
__device__ float g_bev[HDIM];
__device__ float g_Q[(size_t)TOK*HDIM];
__device__ float g_K[(size_t)TOK*HDIM];
__device__ float g_V[(size_t)TOK*HDIM];
__device__ float g_r[(size_t)BB*NH*SS];
__device__ float g_AO[(size_t)TOK*HDIM];
__device__ float g_E[(size_t)BB*NH*SS*SS];   // 1 GiB: exp(scores), lower triangle

// ------------------- effective weights: Weff = W + A@Bw (W may be null) ---------
__global__ void weff_kernel(const float* __restrict__ W, const float* __restrict__ A,
                            const float* __restrict__ Bw, float* __restrict__ out)
{
    int idx = blockIdx.x * 256 + threadIdx.x;   // over DMODEL*HDIM
    int i = idx >> 10;
    int j = idx & 1023;
    float acc = W ? W[idx] : 0.f;
#pragma unroll
    for (int r = 0; r < RK; r++) acc += A[i*RK + r] * Bw[r*HDIM + j];
    out[idx] = acc;
}

// bias_eff[j] = Wb[j] + Bb[j] + sum_r Ab[r]*Bw[r,j]
__global__ void beff_kernel(const float* __restrict__ Wb, const float* __restrict__ Ab,
                            const float* __restrict__ Bw, const float* __restrict__ Bb,
                            float* __restrict__ out)
{
    int j = blockIdx.x * 256 + threadIdx.x;
    float acc = Wb[j] + Bb[j];
#pragma unroll
    for (int r = 0; r < RK; r++) acc += Ab[r] * Bw[r*HDIM + j];
    out[j] = acc;
}

// ------------------- SGEMM: C[M,N] = A[M,K]@W[K,N] (+ A2@W2) + bias -------------
// BM=128, BN=64, BK=16, 256 threads, 8x4 micro-tile per thread.
__global__ __launch_bounds__(256) void sgemm_bias(
    const float* __restrict__ A,  const float* __restrict__ W,
    const float* __restrict__ A2, const float* __restrict__ W2,
    const float* __restrict__ bias, float* __restrict__ C,
    int M, int N, int K)
{
    __shared__ float As[16][128];   // [k][m]
    __shared__ float Bs[16][64];    // [k][n]
    int tid = threadIdx.x;
    int tx = tid & 15, ty = tid >> 4;
    int m0 = blockIdx.y * 128;
    int n0 = blockIdx.x * 64;

    float acc[8][4];
#pragma unroll
    for (int i = 0; i < 8; i++)
#pragma unroll
        for (int j = 0; j < 4; j++) acc[i][j] = 0.f;

    int npass = A2 ? 2 : 1;
    for (int pass = 0; pass < npass; ++pass) {
        const float* Ap = pass ? A2 : A;
        const float* Wp = pass ? W2 : W;
        for (int k0 = 0; k0 < K; k0 += 16) {
            __syncthreads();
            // A tile 128x16 (512 float4)
#pragma unroll
            for (int l = 0; l < 2; l++) {
                int i4 = tid + l * 256;
                int row = i4 >> 2;
                int kq  = (i4 & 3) * 4;
                float4 v = *(const float4*)&Ap[(size_t)(m0 + row) * K + k0 + kq];
                As[kq+0][row] = v.x; As[kq+1][row] = v.y;
                As[kq+2][row] = v.z; As[kq+3][row] = v.w;
            }
            // W tile 16x64 (256 float4)
            {
                int row = tid >> 4;
                int c4  = (tid & 15) * 4;
                float4 v = *(const float4*)&Wp[(size_t)(k0 + row) * N + n0 + c4];
                *(float4*)&Bs[row][c4] = v;
            }
            __syncthreads();
#pragma unroll
            for (int kk = 0; kk < 16; kk++) {
                float a[8], b[4];
#pragma unroll
                for (int i = 0; i < 8; i++) a[i] = As[kk][ty*8 + i];
#pragma unroll
                for (int j = 0; j < 4; j++) b[j] = Bs[kk][tx*4 + j];
#pragma unroll
                for (int i = 0; i < 8; i++)
#pragma unroll
                    for (int j = 0; j < 4; j++)
                        acc[i][j] += a[i] * b[j];
            }
        }
    }
#pragma unroll
    for (int i = 0; i < 8; i++) {
        int m = m0 + ty*8 + i;
        float4 o;
        o.x = acc[i][0] + bias[n0 + tx*4 + 0];
        o.y = acc[i][1] + bias[n0 + tx*4 + 1];
        o.z = acc[i][2] + bias[n0 + tx*4 + 2];
        o.w = acc[i][3] + bias[n0 + tx*4 + 3];
        *(float4*)&C[(size_t)m * N + n0 + tx*4] = o;
    }
}

// ------------------- pass 1: E = exp(scores) (masked), column sums --------------
// grid (S/64 key-tiles, H, B); block 256 (16x16); q-tile 128, k-tile 64.
__global__ __launch_bounds__(256) void attn_pass1()
{
    __shared__ float Qs[128][64];   // [q][d]
    __shared__ float Ks[64][64];    // [d][k] (transposed for conflict-free reads)
    int tid = threadIdx.x;
    int tx = tid & 15, ty = tid >> 4;
    int k0 = blockIdx.x * 64;
    int h = blockIdx.y, b = blockIdx.z;
    int bh = b * NH + h;

    // load K tile transposed (once per block)
#pragma unroll
    for (int l = 0; l < 4; l++) {
        int i4 = tid + l * 256;            // 64*16 float4
        int krow = i4 >> 4;
        int d4 = (i4 & 15) * 4;
        float4 v = *(const float4*)&g_K[(size_t)(b*SS + k0 + krow) * HDIM + h*HD + d4];
        Ks[d4+0][krow] = v.x; Ks[d4+1][krow] = v.y;
        Ks[d4+2][krow] = v.z; Ks[d4+3][krow] = v.w;
    }

    float csum[4] = {0.f, 0.f, 0.f, 0.f};
    int q0start = (k0 / 128) * 128;

    for (int q0 = q0start; q0 < SS; q0 += 128) {
        __syncthreads();
        // load Q tile [128][64]
#pragma unroll
        for (int l = 0; l < 8; l++) {
            int i4 = tid + l * 256;
            int row = i4 >> 4;
            int d4 = (i4 & 15) * 4;
            *(float4*)&Qs[row][d4] =
                *(const float4*)&g_Q[(size_t)(b*SS + q0 + row) * HDIM + h*HD + d4];
        }
        __syncthreads();

        float sc[8][4];
#pragma unroll
        for (int i = 0; i < 8; i++)
#pragma unroll
            for (int j = 0; j < 4; j++) sc[i][j] = 0.f;

#pragma unroll 8
        for (int d = 0; d < 64; d++) {
            float a[8], kv[4];
#pragma unroll
            for (int i = 0; i < 8; i++) a[i] = Qs[ty*8 + i][d];
#pragma unroll
            for (int j = 0; j < 4; j++) kv[j] = Ks[d][tx*4 + j];
#pragma unroll
            for (int i = 0; i < 8; i++)
#pragma unroll
                for (int j = 0; j < 4; j++)
                    sc[i][j] += a[i] * kv[j];
        }

        int kbase = k0 + tx*4;
#pragma unroll
        for (int i = 0; i < 8; i++) {
            int q = q0 + ty*8 + i;
            float4 e;
            e.x = (q >= kbase + 0) ? __expf(sc[i][0]) : 0.f;
            e.y = (q >= kbase + 1) ? __expf(sc[i][1]) : 0.f;
            e.z = (q >= kbase + 2) ? __expf(sc[i][2]) : 0.f;
            e.w = (q >= kbase + 3) ? __expf(sc[i][3]) : 0.f;
            csum[0] += e.x; csum[1] += e.y; csum[2] += e.z; csum[3] += e.w;
            *(float4*)&g_E[((size_t)bh * SS + q) * SS + kbase] = e;
        }
    }

    // column-sum reduction across ty (reuse Qs as scratch)
    __syncthreads();
    float* red = &Qs[0][0];
    red[ty*64 + tx*4 + 0] = csum[0];
    red[ty*64 + tx*4 + 1] = csum[1];
    red[ty*64 + tx*4 + 2] = csum[2];
    red[ty*64 + tx*4 + 3] = csum[3];
    __syncthreads();
    if (tid < 64) {
        float s = 0.f;
#pragma unroll
        for (int t = 0; t < 16; t++) s += red[t*64 + tid];
        // fold in the post-softmax 1/sqrt(D) = 1/8 scale
        g_r[(size_t)bh * SS + k0 + tid] = 1.0f / (s * 8.0f);
    }
}

// ------------------- pass 2: attO = (E * r[k]) @ V -------------------------------
// grid (S/128 q-tiles, H, B); block 256; BM=128(q), BN=64(d), BK=16(k).
__global__ __launch_bounds__(256) void attn_pass2()
{
    __shared__ float Es[16][128];   // [k][q]
    __shared__ float Vs[16][64];    // [k][d], pre-scaled by r[k]
    int tid = threadIdx.x;
    int tx = tid & 15, ty = tid >> 4;
    int q0 = blockIdx.x * 128;
    int h = blockIdx.y, b = blockIdx.z;
    int bh = b * NH + h;

    float acc[8][4];
#pragma unroll
    for (int i = 0; i < 8; i++)
#pragma unroll
        for (int j = 0; j < 4; j++) acc[i][j] = 0.f;

    int nk = q0 + 128;   // causal: only k < q0+128 can contribute (E==0 above diag)
    for (int k0 = 0; k0 < nk; k0 += 16) {
        __syncthreads();
        // E tile 128x16, store transposed (512 float4)
#pragma unroll
        for (int l = 0; l < 2; l++) {
            int i4 = tid + l * 256;
            int row = i4 >> 2;
            int kc4 = (i4 & 3) * 4;
            float4 v = *(const float4*)&g_E[((size_t)bh*SS + q0 + row) * SS + k0 + kc4];
            Es[kc4+0][row] = v.x; Es[kc4+1][row] = v.y;
            Es[kc4+2][row] = v.z; Es[kc4+3][row] = v.w;
        }
        // V tile 16x64 scaled by r[k]
        {
            int row = tid >> 4;
            int c4  = (tid & 15) * 4;
            float sc = g_r[(size_t)bh*SS + k0 + row];
            float4 v = *(const float4*)&g_V[(size_t)(b*SS + k0 + row) * HDIM + h*HD + c4];
            Vs[row][c4+0] = v.x * sc; Vs[row][c4+1] = v.y * sc;
            Vs[row][c4+2] = v.z * sc; Vs[row][c4+3] = v.w * sc;
        }
        __syncthreads();
#pragma unroll
        for (int kk = 0; kk < 16; kk++) {
            float a[8], bv[4];
#pragma unroll
            for (int i = 0; i < 8; i++) a[i] = Es[kk][ty*8 + i];
#pragma unroll
            for (int j = 0; j < 4; j++) bv[j] = Vs[kk][tx*4 + j];
#pragma unroll
            for (int i = 0; i < 8; i++)
#pragma unroll
                for (int j = 0; j < 4; j++)
                    acc[i][j] += a[i] * bv[j];
        }
    }
#pragma unroll
    for (int i = 0; i < 8; i++) {
        int q = q0 + ty*8 + i;
        float4 o; o.x = acc[i][0]; o.y = acc[i][1]; o.z = acc[i][2]; o.w = acc[i][3];
        *(float4*)&g_AO[(size_t)(b*SS + q) * HDIM + h*HD + tx*4] = o;
    }
}

// ------------------- launch ------------------------------------------------------
extern "C" void kernel_launch(void* const* d_in, const int* in_sizes, int n_in,
                              void* d_out, int out_size)
{
    const float* queries = (const float*)d_in[0];
    const float* keys    = (const float*)d_in[1];
    const float* values  = (const float*)d_in[2];
    const float* Wq_w = (const float*)d_in[3];  const float* Wq_b = (const float*)d_in[4];
    const float* Wk_w = (const float*)d_in[5];  const float* Wk_b = (const float*)d_in[6];
    const float* Wv_w = (const float*)d_in[7];  const float* Wv_b = (const float*)d_in[8];
    const float* Aq_w = (const float*)d_in[9];  const float* Aq_b = (const float*)d_in[10];
    const float* Bq_w = (const float*)d_in[11]; const float* Bq_b = (const float*)d_in[12];
    const float* Ak_w = (const float*)d_in[13]; const float* Ak_b = (const float*)d_in[14];
    const float* Bk_w = (const float*)d_in[15]; const float* Bk_b = (const float*)d_in[16];
    const float* Av_w = (const float*)d_in[17]; const float* Av_b = (const float*)d_in[18];
    const float* Bv_w = (const float*)d_in[19]; const float* Bv_b = (const float*)d_in[20];
    const float* Wo_w = (const float*)d_in[21]; const float* Wo_b = (const float*)d_in[22];
    float* out = (float*)d_out;

    void *pWeq, *pWek, *pWvL, *pbeq, *pbek, *pbev, *pQ, *pK, *pV, *pAO;
    cudaGetSymbolAddress(&pWeq, g_Weq);
    cudaGetSymbolAddress(&pWek, g_Wek);
    cudaGetSymbolAddress(&pWvL, g_WvL);
    cudaGetSymbolAddress(&pbeq, g_beq);
    cudaGetSymbolAddress(&pbek, g_bek);
    cudaGetSymbolAddress(&pbev, g_bev);
    cudaGetSymbolAddress(&pQ, g_Q);
    cudaGetSymbolAddress(&pK, g_K);
    cudaGetSymbolAddress(&pV, g_V);
    cudaGetSymbolAddress(&pAO, g_AO);

    // fold LoRA into effective weights / biases
    weff_kernel<<<DMODEL*HDIM/256, 256>>>(Wq_w, Aq_w, Bq_w, (float*)pWeq);
    weff_kernel<<<DMODEL*HDIM/256, 256>>>(Wk_w, Ak_w, Bk_w, (float*)pWek);
    weff_kernel<<<DMODEL*HDIM/256, 256>>>(nullptr, Av_w, Bv_w, (float*)pWvL);
    beff_kernel<<<HDIM/256, 256>>>(Wq_b, Aq_b, Bq_w, Bq_b, (float*)pbeq);
    beff_kernel<<<HDIM/256, 256>>>(Wk_b, Ak_b, Bk_w, Bk_b, (float*)pbek);
    beff_kernel<<<HDIM/256, 256>>>(Wv_b, Av_b, Bv_w, Bv_b, (float*)pbev);

    dim3 ggrid(HDIM/64, TOK/128);
    // Q = queries @ Weq + beq ; K = keys @ Wek + bek
    sgemm_bias<<<ggrid, 256>>>(queries, (const float*)pWeq, nullptr, nullptr,
                               (const float*)pbeq, (float*)pQ, TOK, HDIM, DMODEL);
    sgemm_bias<<<ggrid, 256>>>(keys, (const float*)pWek, nullptr, nullptr,
                               (const float*)pbek, (float*)pK, TOK, HDIM, DMODEL);
    // V = values @ Wv + keys @ (Av@Bv) + bev   (reference uses keys for the V-LoRA)
    sgemm_bias<<<ggrid, 256>>>(values, Wv_w, keys, (const float*)pWvL,
                               (const float*)pbev, (float*)pV, TOK, HDIM, DMODEL);

    // attention: column-softmax over query axis, causal mask, scale 1/8 after softmax
    attn_pass1<<<dim3(SS/64, NH, BB), 256>>>();
    attn_pass2<<<dim3(SS/128, NH, BB), 256>>>();

    // output projection
    sgemm_bias<<<dim3(DMODEL/64, TOK/128), 256>>>(
        (const float*)pAO, Wo_w, nullptr, nullptr, Wo_b, out, TOK, DMODEL, DMODEL);
}

// round 3
// speedup vs baseline: 1.5315x; 1.5315x over previous
#include <cuda_runtime.h>
#include <cuda_bf16.h>
#include <math.h>
#include <stdint.h>

#define BB     4
#define SS     2048
#define DMODEL 1024
#define NH     16
#define HD     64
#define HDIM   1024
#define RK     8
#define TOK    (BB*SS)   // 8192

// ------------------- device scratch (static; allocation-free) -------------------
__device__ float g_beq[HDIM];
__device__ float g_bek[HDIM];
__device__ float g_bev[HDIM];
__device__ float g_Q[(size_t)TOK*HDIM];
__device__ float g_K[(size_t)TOK*HDIM];
__device__ float g_V[(size_t)TOK*HDIM];
__device__ float g_r[(size_t)BB*NH*SS];
__device__ float g_E[(size_t)BB*NH*SS*SS];   // 1 GiB exp(scores)

// split-bf16 activations [M,K] K-major
__device__ __nv_bfloat16 g_qh[(size_t)TOK*DMODEL];
__device__ __nv_bfloat16 g_ql[(size_t)TOK*DMODEL];
__device__ __nv_bfloat16 g_kh[(size_t)TOK*DMODEL];
__device__ __nv_bfloat16 g_kl[(size_t)TOK*DMODEL];
__device__ __nv_bfloat16 g_vh[(size_t)TOK*DMODEL];
__device__ __nv_bfloat16 g_vl[(size_t)TOK*DMODEL];
__device__ __nv_bfloat16 g_aoh[(size_t)TOK*HDIM];
__device__ __nv_bfloat16 g_aol[(size_t)TOK*HDIM];
// split-bf16 transposed weights [N,K]
__device__ __nv_bfloat16 g_wqh[DMODEL*HDIM], g_wql[DMODEL*HDIM];
__device__ __nv_bfloat16 g_wkh[DMODEL*HDIM], g_wkl[DMODEL*HDIM];
__device__ __nv_bfloat16 g_wvh[DMODEL*HDIM], g_wvl[DMODEL*HDIM];
__device__ __nv_bfloat16 g_wvLh[DMODEL*HDIM], g_wvLl[DMODEL*HDIM];
__device__ __nv_bfloat16 g_woh[DMODEL*HDIM], g_wol[DMODEL*HDIM];

// ------------------- helpers ------------------------------------------------------
__device__ __forceinline__ uint32_t smem_u32(const void* p) {
    uint32_t a;
    asm("{ .reg .u64 t; cvta.to.shared.u64 t, %1; cvt.u32.u64 %0, t; }" : "=r"(a) : "l"(p));
    return a;
}
__device__ __forceinline__ void cpa16(uint32_t dst, const void* src) {
    asm volatile("cp.async.cg.shared.global [%0], [%1], 16;"
                 :: "r"(dst), "l"(__cvta_generic_to_global(src)));
}
#define CPA_COMMIT() asm volatile("cp.async.commit_group;")
#define CPA_WAIT1()  asm volatile("cp.async.wait_group 1;")

#define LDSM4(r, a) \
    asm volatile("ldmatrix.sync.aligned.m8n8.x4.shared.b16 {%0,%1,%2,%3}, [%4];" \
        : "=r"((r)[0]), "=r"((r)[1]), "=r"((r)[2]), "=r"((r)[3]) : "r"(a))

#define MMA16816(c, a, b0, b1) \
    asm volatile("mma.sync.aligned.m16n8k16.row.col.f32.bf16.bf16.f32 " \
        "{%0,%1,%2,%3}, {%4,%5,%6,%7}, {%8,%9}, {%0,%1,%2,%3};" \
        : "+f"((c)[0]), "+f"((c)[1]), "+f"((c)[2]), "+f"((c)[3]) \
        : "r"((a)[0]), "r"((a)[1]), "r"((a)[2]), "r"((a)[3]), "r"(b0), "r"(b1))

// ------------------- prep kernels ------------------------------------------------
__global__ void beff_kernel(const float* __restrict__ Wb, const float* __restrict__ Ab,
                            const float* __restrict__ Bw, const float* __restrict__ Bb,
                            float* __restrict__ out)
{
    int j = blockIdx.x * 256 + threadIdx.x;
    float acc = Wb[j] + Bb[j];
#pragma unroll
    for (int r = 0; r < RK; r++) acc += Ab[r] * Bw[r*HDIM + j];
    out[j] = acc;
}

// Weff[k,n] = (W?W:0) + (A? A@Bw : 0); transpose + hi/lo split to [n,k]
__global__ __launch_bounds__(256) void wprep_kernel(
    const float* __restrict__ W, const float* __restrict__ A, const float* __restrict__ Bw,
    __nv_bfloat16* __restrict__ hi, __nv_bfloat16* __restrict__ lo)
{
    __shared__ float t[32][33];
    int kb = blockIdx.x * 32, nb = blockIdx.y * 32;
    int x = threadIdx.x & 31, y = threadIdx.x >> 5;
#pragma unroll
    for (int i = y; i < 32; i += 8) {
        int k = kb + i, n = nb + x;
        float v = W ? W[(size_t)k*HDIM + n] : 0.f;
        if (A) {
#pragma unroll
            for (int r = 0; r < RK; r++) v += A[k*RK + r] * Bw[r*HDIM + n];
        }
        t[i][x] = v;
    }
    __syncthreads();
#pragma unroll
    for (int i = y; i < 32; i += 8) {
        int n = nb + i, k = kb + x;
        float v = t[x][i];
        __nv_bfloat16 h = __float2bfloat16(v);
        hi[(size_t)n*DMODEL + k] = h;
        lo[(size_t)n*DMODEL + k] = __float2bfloat16(v - __bfloat162float(h));
    }
}

__global__ void actconv_kernel(const float* __restrict__ X,
                               __nv_bfloat16* __restrict__ hi, __nv_bfloat16* __restrict__ lo)
{
    size_t i = ((size_t)blockIdx.x * 256 + threadIdx.x) * 4;
    float4 v = *(const float4*)&X[i];
    __nv_bfloat16 h0 = __float2bfloat16(v.x), h1 = __float2bfloat16(v.y);
    __nv_bfloat16 h2 = __float2bfloat16(v.z), h3 = __float2bfloat16(v.w);
    __nv_bfloat162 ph0 = {h0, h1}, ph1 = {h2, h3};
    __nv_bfloat162 pl0 = {__float2bfloat16(v.x - __bfloat162float(h0)),
                          __float2bfloat16(v.y - __bfloat162float(h1))};
    __nv_bfloat162 pl1 = {__float2bfloat16(v.z - __bfloat162float(h2)),
                          __float2bfloat16(v.w - __bfloat162float(h3))};
    *(__nv_bfloat162*)&hi[i]   = ph0;  *(__nv_bfloat162*)&hi[i+2] = ph1;
    *(__nv_bfloat162*)&lo[i]   = pl0;  *(__nv_bfloat162*)&lo[i+2] = pl1;
}

// ------------------- mma.sync split-bf16 GEMM ------------------------------------
// out[M,1024] = sum_seg A_seg[M,1024] @ B_seg[N,1024]^T + bias.
// 128x128 CTA tile, 8 warps (2x4), warp tile 64x32, BK=32, 2-stage cp.async.
// SMEM tile layout: 128 rows x 80B pitch (64B data), tiles Ah|Al|Bh|Bl @10240B.
static constexpr int STAGE_BYTES = 40960;
static constexpr int GEMM_SMEM   = 2 * STAGE_BYTES;   // 81920

__global__ __launch_bounds__(256, 1)
void gemm_mma(const __nv_bfloat16* __restrict__ A1h, const __nv_bfloat16* __restrict__ A1l,
              const __nv_bfloat16* __restrict__ B1h, const __nv_bfloat16* __restrict__ B1l,
              const __nv_bfloat16* __restrict__ A2h, const __nv_bfloat16* __restrict__ A2l,
              const __nv_bfloat16* __restrict__ B2h, const __nv_bfloat16* __restrict__ B2l,
              const float* __restrict__ bias, float* __restrict__ out, int nchunks)
{
    extern __shared__ char smem[];
    const uint32_t sb = smem_u32(smem);
    const int tid  = threadIdx.x;
    const int lane = tid & 31;
    const int warp = tid >> 5;
    const int wm = warp >> 2, wn = warp & 3;
    const int m0 = blockIdx.y * 128, n0 = blockIdx.x * 128;

    float acc[4][4][4];
#pragma unroll
    for (int i = 0; i < 4; i++)
#pragma unroll
        for (int j = 0; j < 4; j++)
#pragma unroll
            for (int k = 0; k < 4; k++) acc[i][j][k] = 0.f;

    auto load_stage = [&](int st, int chunk) {
        int seg = chunk >> 5;          // 32 chunks of K=32 per 1024-K segment
        int k0  = (chunk & 31) * 32;
        const __nv_bfloat16* p0 = seg ? A2h : A1h;
        const __nv_bfloat16* p1 = seg ? A2l : A1l;
        const __nv_bfloat16* p2 = seg ? B2h : B1h;
        const __nv_bfloat16* p3 = seg ? B2l : B1l;
        const __nv_bfloat16* tp[4] = {p0, p1, p2, p3};
        uint32_t sbase = sb + st * STAGE_BYTES;
#pragma unroll
        for (int i = 0; i < 8; i++) {
            const int t = i >> 1;                  // tile index (constant per i)
            int j = (i & 1) ? tid + 256 : tid;     // 0..511 within tile
            int row = j >> 2, sg = j & 3;
            int r0 = (t < 2) ? m0 : n0;
            cpa16(sbase + t * 10240 + row * 80 + sg * 16,
                  tp[t] + (size_t)(r0 + row) * 1024 + k0 + sg * 8);
        }
    };

    auto compute_stage = [&](int st) {
        uint32_t ab = sb + st * STAGE_BYTES;
#pragma unroll
        for (int kk = 0; kk < 2; kk++) {
            uint32_t ah[4][4], al[4][4], bh[4][2], bl[4][2];
            uint32_t aoff = (uint32_t)(wm*64 + (lane & 15)) * 80
                          + (uint32_t)(kk*16 + (lane >> 4) * 8) * 2;
#pragma unroll
            for (int mt = 0; mt < 4; mt++) {
                LDSM4(ah[mt], ab + aoff + mt * (16*80));
                LDSM4(al[mt], ab + 10240 + aoff + mt * (16*80));
            }
            uint32_t boff = (uint32_t)(wn*32 + (lane & 7) + ((lane >> 4) << 3)) * 80
                          + (uint32_t)(kk*16 + ((lane >> 3) & 1) * 8) * 2;
            {
                uint32_t t0[4], t1[4];
                LDSM4(t0, ab + 20480 + boff);
                LDSM4(t1, ab + 20480 + boff + 16*80);
                bh[0][0]=t0[0]; bh[0][1]=t0[1]; bh[1][0]=t0[2]; bh[1][1]=t0[3];
                bh[2][0]=t1[0]; bh[2][1]=t1[1]; bh[3][0]=t1[2]; bh[3][1]=t1[3];
                LDSM4(t0, ab + 30720 + boff);
                LDSM4(t1, ab + 30720 + boff + 16*80);
                bl[0][0]=t0[0]; bl[0][1]=t0[1]; bl[1][0]=t0[2]; bl[1][1]=t0[3];
                bl[2][0]=t1[0]; bl[2][1]=t1[1]; bl[3][0]=t1[2]; bl[3][1]=t1[3];
            }
#pragma unroll
            for (int mt = 0; mt < 4; mt++)
#pragma unroll
                for (int nt = 0; nt < 4; nt++) {
                    MMA16816(acc[mt][nt], ah[mt], bh[nt][0], bh[nt][1]);
                    MMA16816(acc[mt][nt], ah[mt], bl[nt][0], bl[nt][1]);
                    MMA16816(acc[mt][nt], al[mt], bh[nt][0], bh[nt][1]);
                }
        }
    };

    load_stage(0, 0);
    CPA_COMMIT();
    if (nchunks > 1) load_stage(1, 1);
    CPA_COMMIT();

    for (int c = 0; c < nchunks; c++) {
        CPA_WAIT1();
        __syncthreads();
        compute_stage(c & 1);
        __syncthreads();
        if (c + 2 < nchunks) load_stage(c & 1, c + 2);
        CPA_COMMIT();
    }

    // epilogue
    int r_ = lane >> 2, c_ = (lane & 3) * 2;
#pragma unroll
    for (int mt = 0; mt < 4; mt++)
#pragma unroll
        for (int nt = 0; nt < 4; nt++) {
            int row = m0 + wm*64 + mt*16 + r_;
            int col = n0 + wn*32 + nt*8 + c_;
            float b0 = bias[col], b1 = bias[col + 1];
            float2 v0 = {acc[mt][nt][0] + b0, acc[mt][nt][1] + b1};
            float2 v1 = {acc[mt][nt][2] + b0, acc[mt][nt][3] + b1};
            *(float2*)&out[(size_t)row * 1024 + col] = v0;
            *(float2*)&out[(size_t)(row + 8) * 1024 + col] = v1;
        }
}

// ------------------- pass 1: E = exp(scores) (masked), column sums --------------
__global__ __launch_bounds__(256) void attn_pass1()
{
    __shared__ float Qs[128][64];
    __shared__ float Ks[64][64];
    int tid = threadIdx.x;
    int tx = tid & 15, ty = tid >> 4;
    int k0 = blockIdx.x * 64;
    int h = blockIdx.y, b = blockIdx.z;
    int bh = b * NH + h;

#pragma unroll
    for (int l = 0; l < 4; l++) {
        int i4 = tid + l * 256;
        int krow = i4 >> 4;
        int d4 = (i4 & 15) * 4;
        float4 v = *(const float4*)&g_K[(size_t)(b*SS + k0 + krow) * HDIM + h*HD + d4];
        Ks[d4+0][krow] = v.x; Ks[d4+1][krow] = v.y;
        Ks[d4+2][krow] = v.z; Ks[d4+3][krow] = v.w;
    }

    float csum[4] = {0.f, 0.f, 0.f, 0.f};
    int q0start = (k0 / 128) * 128;

    for (int q0 = q0start; q0 < SS; q0 += 128) {
        __syncthreads();
#pragma unroll
        for (int l = 0; l < 8; l++) {
            int i4 = tid + l * 256;
            int row = i4 >> 4;
            int d4 = (i4 & 15) * 4;
            *(float4*)&Qs[row][d4] =
                *(const float4*)&g_Q[(size_t)(b*SS + q0 + row) * HDIM + h*HD + d4];
        }
        __syncthreads();

        float sc[8][4];
#pragma unroll
        for (int i = 0; i < 8; i++)
#pragma unroll
            for (int j = 0; j < 4; j++) sc[i][j] = 0.f;

#pragma unroll 8
        for (int d = 0; d < 64; d++) {
            float a[8], kv[4];
#pragma unroll
            for (int i = 0; i < 8; i++) a[i] = Qs[ty*8 + i][d];
#pragma unroll
            for (int j = 0; j < 4; j++) kv[j] = Ks[d][tx*4 + j];
#pragma unroll
            for (int i = 0; i < 8; i++)
#pragma unroll
                for (int j = 0; j < 4; j++)
                    sc[i][j] += a[i] * kv[j];
        }

        int kbase = k0 + tx*4;
#pragma unroll
        for (int i = 0; i < 8; i++) {
            int q = q0 + ty*8 + i;
            float4 e;
            e.x = (q >= kbase + 0) ? __expf(sc[i][0]) : 0.f;
            e.y = (q >= kbase + 1) ? __expf(sc[i][1]) : 0.f;
            e.z = (q >= kbase + 2) ? __expf(sc[i][2]) : 0.f;
            e.w = (q >= kbase + 3) ? __expf(sc[i][3]) : 0.f;
            csum[0] += e.x; csum[1] += e.y; csum[2] += e.z; csum[3] += e.w;
            *(float4*)&g_E[((size_t)bh * SS + q) * SS + kbase] = e;
        }
    }

    __syncthreads();
    float* red = &Qs[0][0];
    red[ty*64 + tx*4 + 0] = csum[0];
    red[ty*64 + tx*4 + 1] = csum[1];
    red[ty*64 + tx*4 + 2] = csum[2];
    red[ty*64 + tx*4 + 3] = csum[3];
    __syncthreads();
    if (tid < 64) {
        float s = 0.f;
#pragma unroll
        for (int t = 0; t < 16; t++) s += red[t*64 + tid];
        g_r[(size_t)bh * SS + k0 + tid] = 1.0f / (s * 8.0f);
    }
}

// ------------------- pass 2: attO = (E * r[k]) @ V, output hi/lo bf16 -----------
__global__ __launch_bounds__(256) void attn_pass2()
{
    __shared__ float Es[16][128];
    __shared__ float Vs[16][64];
    int tid = threadIdx.x;
    int tx = tid & 15, ty = tid >> 4;
    int q0 = blockIdx.x * 128;
    int h = blockIdx.y, b = blockIdx.z;
    int bh = b * NH + h;

    float acc[8][4];
#pragma unroll
    for (int i = 0; i < 8; i++)
#pragma unroll
        for (int j = 0; j < 4; j++) acc[i][j] = 0.f;

    int nk = q0 + 128;
    for (int k0 = 0; k0 < nk; k0 += 16) {
        __syncthreads();
#pragma unroll
        for (int l = 0; l < 2; l++) {
            int i4 = tid + l * 256;
            int row = i4 >> 2;
            int kc4 = (i4 & 3) * 4;
            float4 v = *(const float4*)&g_E[((size_t)bh*SS + q0 + row) * SS + k0 + kc4];
            Es[kc4+0][row] = v.x; Es[kc4+1][row] = v.y;
            Es[kc4+2][row] = v.z; Es[kc4+3][row] = v.w;
        }
        {
            int row = tid >> 4;
            int c4  = (tid & 15) * 4;
            float sc = g_r[(size_t)bh*SS + k0 + row];
            float4 v = *(const float4*)&g_V[(size_t)(b*SS + k0 + row) * HDIM + h*HD + c4];
            Vs[row][c4+0] = v.x * sc; Vs[row][c4+1] = v.y * sc;
            Vs[row][c4+2] = v.z * sc; Vs[row][c4+3] = v.w * sc;
        }
        __syncthreads();
#pragma unroll
        for (int kk = 0; kk < 16; kk++) {
            float a[8], bv[4];
#pragma unroll
            for (int i = 0; i < 8; i++) a[i] = Es[kk][ty*8 + i];
#pragma unroll
            for (int j = 0; j < 4; j++) bv[j] = Vs[kk][tx*4 + j];
#pragma unroll
            for (int i = 0; i < 8; i++)
#pragma unroll
                for (int j = 0; j < 4; j++)
                    acc[i][j] += a[i] * bv[j];
        }
    }
#pragma unroll
    for (int i = 0; i < 8; i++) {
        int q = q0 + ty*8 + i;
        size_t idx = (size_t)(b*SS + q) * HDIM + h*HD + tx*4;
        __nv_bfloat16 h0 = __float2bfloat16(acc[i][0]);
        __nv_bfloat16 h1 = __float2bfloat16(acc[i][1]);
        __nv_bfloat16 h2 = __float2bfloat16(acc[i][2]);
        __nv_bfloat16 h3 = __float2bfloat16(acc[i][3]);
        __nv_bfloat162 ph0 = {h0, h1}, ph1 = {h2, h3};
        __nv_bfloat162 pl0 = {__float2bfloat16(acc[i][0] - __bfloat162float(h0)),
                              __float2bfloat16(acc[i][1] - __bfloat162float(h1))};
        __nv_bfloat162 pl1 = {__float2bfloat16(acc[i][2] - __bfloat162float(h2)),
                              __float2bfloat16(acc[i][3] - __bfloat162float(h3))};
        *(__nv_bfloat162*)&g_aoh[idx]   = ph0; *(__nv_bfloat162*)&g_aoh[idx+2] = ph1;
        *(__nv_bfloat162*)&g_aol[idx]   = pl0; *(__nv_bfloat162*)&g_aol[idx+2] = pl1;
    }
}

// ------------------- launch ------------------------------------------------------
extern "C" void kernel_launch(void* const* d_in, const int* in_sizes, int n_in,
                              void* d_out, int out_size)
{
    const float* queries = (const float*)d_in[0];
    const float* keys    = (const float*)d_in[1];
    const float* values  = (const float*)d_in[2];
    const float* Wq_w = (const float*)d_in[3];  const float* Wq_b = (const float*)d_in[4];
    const float* Wk_w = (const float*)d_in[5];  const float* Wk_b = (const float*)d_in[6];
    const float* Wv_w = (const float*)d_in[7];  const float* Wv_b = (const float*)d_in[8];
    const float* Aq_w = (const float*)d_in[9];
    const float* Aq_b = (const float*)d_in[10];
    const float* Bq_w = (const float*)d_in[11]; const float* Bq_b = (const float*)d_in[12];
    const float* Ak_w = (const float*)d_in[13]; const float* Ak_b = (const float*)d_in[14];
    const float* Bk_w = (const float*)d_in[15]; const float* Bk_b = (const float*)d_in[16];
    const float* Av_w = (const float*)d_in[17]; const float* Av_b = (const float*)d_in[18];
    const float* Bv_w = (const float*)d_in[19]; const float* Bv_b = (const float*)d_in[20];
    const float* Wo_w = (const float*)d_in[21]; const float* Wo_b = (const float*)d_in[22];
    float* out = (float*)d_out;

    cudaFuncSetAttribute(gemm_mma, cudaFuncAttributeMaxDynamicSharedMemorySize, GEMM_SMEM);

    void *pbeq, *pbek, *pbev, *pQ, *pK, *pV;
    void *pqh, *pql, *pkh, *pkl, *pvh, *pvl, *paoh, *paol;
    void *pwqh, *pwql, *pwkh, *pwkl, *pwvh, *pwvl, *pwvLh, *pwvLl, *pwoh, *pwol;
    cudaGetSymbolAddress(&pbeq, g_beq); cudaGetSymbolAddress(&pbek, g_bek);
    cudaGetSymbolAddress(&pbev, g_bev);
    cudaGetSymbolAddress(&pQ, g_Q); cudaGetSymbolAddress(&pK, g_K); cudaGetSymbolAddress(&pV, g_V);
    cudaGetSymbolAddress(&pqh, g_qh); cudaGetSymbolAddress(&pql, g_ql);
    cudaGetSymbolAddress(&pkh, g_kh); cudaGetSymbolAddress(&pkl, g_kl);
    cudaGetSymbolAddress(&pvh, g_vh); cudaGetSymbolAddress(&pvl, g_vl);
    cudaGetSymbolAddress(&paoh, g_aoh); cudaGetSymbolAddress(&paol, g_aol);
    cudaGetSymbolAddress(&pwqh, g_wqh); cudaGetSymbolAddress(&pwql, g_wql);
    cudaGetSymbolAddress(&pwkh, g_wkh); cudaGetSymbolAddress(&pwkl, g_wkl);
    cudaGetSymbolAddress(&pwvh, g_wvh); cudaGetSymbolAddress(&pwvl, g_wvl);
    cudaGetSymbolAddress(&pwvLh, g_wvLh); cudaGetSymbolAddress(&pwvLl, g_wvLl);
    cudaGetSymbolAddress(&pwoh, g_woh); cudaGetSymbolAddress(&pwol, g_wol);

    int actblocks = (TOK * DMODEL / 4) / 256;
    actconv_kernel<<<actblocks, 256>>>(queries, (__nv_bfloat16*)pqh, (__nv_bfloat16*)pql);
    actconv_kernel<<<actblocks, 256>>>(keys,    (__nv_bfloat16*)pkh, (__nv_bfloat16*)pkl);
    actconv_kernel<<<actblocks, 256>>>(values,  (__nv_bfloat16*)pvh, (__nv_bfloat16*)pvl);

    dim3 wgrid(DMODEL/32, HDIM/32);
    wprep_kernel<<<wgrid, 256>>>(Wq_w, Aq_w, Bq_w, (__nv_bfloat16*)pwqh, (__nv_bfloat16*)pwql);
    wprep_kernel<<<wgrid, 256>>>(Wk_w, Ak_w, Bk_w, (__nv_bfloat16*)pwkh, (__nv_bfloat16*)pwkl);
    wprep_kernel<<<wgrid, 256>>>(Wv_w, nullptr, nullptr, (__nv_bfloat16*)pwvh, (__nv_bfloat16*)pwvl);
    wprep_kernel<<<wgrid, 256>>>(nullptr, Av_w, Bv_w, (__nv_bfloat16*)pwvLh, (__nv_bfloat16*)pwvLl);
    wprep_kernel<<<wgrid, 256>>>(Wo_w, nullptr, nullptr, (__nv_bfloat16*)pwoh, (__nv_bfloat16*)pwol);

    beff_kernel<<<HDIM/256, 256>>>(Wq_b, Aq_b, Bq_w, Bq_b, (float*)pbeq);
    beff_kernel<<<HDIM/256, 256>>>(Wk_b, Ak_b, Bk_w, Bk_b, (float*)pbek);
    beff_kernel<<<HDIM/256, 256>>>(Wv_b, Av_b, Bv_w, Bv_b, (float*)pbev);

    dim3 ggrid(HDIM/128, TOK/128);
    gemm_mma<<<ggrid, 256, GEMM_SMEM>>>(
        (const __nv_bfloat16*)pqh, (const __nv_bfloat16*)pql,
        (const __nv_bfloat16*)pwqh, (const __nv_bfloat16*)pwql,
        nullptr, nullptr, nullptr, nullptr,
        (const float*)pbeq, (float*)pQ, 32);
    gemm_mma<<<ggrid, 256, GEMM_SMEM>>>(
        (const __nv_bfloat16*)pkh, (const __nv_bfloat16*)pkl,
        (const __nv_bfloat16*)pwkh, (const __nv_bfloat16*)pwkl,
        nullptr, nullptr, nullptr, nullptr,
        (const float*)pbek, (float*)pK, 32);
    // V = values@Wv + keys@(Av@Bv) + bev   (reference applies V-LoRA to keys)
    gemm_mma<<<ggrid, 256, GEMM_SMEM>>>(
        (const __nv_bfloat16*)pvh, (const __nv_bfloat16*)pvl,
        (const __nv_bfloat16*)pwvh, (const __nv_bfloat16*)pwvl,
        (const __nv_bfloat16*)pkh, (const __nv_bfloat16*)pkl,
        (const __nv_bfloat16*)pwvLh, (const __nv_bfloat16*)pwvLl,
        (const float*)pbev, (float*)pV, 64);

    attn_pass1<<<dim3(SS/64, NH, BB), 256>>>();
    attn_pass2<<<dim3(SS/128, NH, BB), 256>>>();

    gemm_mma<<<ggrid, 256, GEMM_SMEM>>>(
        (const __nv_bfloat16*)paoh, (const __nv_bfloat16*)paol,
        (const __nv_bfloat16*)pwoh, (const __nv_bfloat16*)pwol,
        nullptr, nullptr, nullptr, nullptr,
        Wo_b, out, 32);
}

// round 4
// speedup vs baseline: 1.9452x; 1.2701x over previous
#include <cuda_runtime.h>
#include <cuda_bf16.h>
#include <math.h>
#include <stdint.h>

#define BB     4
#define SS     2048
#define DMODEL 1024
#define NH     16
#define HD     64
#define HDIM   1024
#define RK     8
#define TOK    (BB*SS)   // 8192

// ------------------- device scratch (static; allocation-free) -------------------
__device__ float g_beq[HDIM];
__device__ float g_bek[HDIM];
__device__ float g_bev[HDIM];
__device__ float g_V[(size_t)TOK*HDIM];            // projected V (fp32)
__device__ float g_colsum[(size_t)BB*NH*SS];       // per-(head,k) exp column sums

// split-bf16 input activations [M,K] K-major
__device__ __nv_bfloat16 g_qh[(size_t)TOK*DMODEL], g_ql[(size_t)TOK*DMODEL];
__device__ __nv_bfloat16 g_kh[(size_t)TOK*DMODEL], g_kl[(size_t)TOK*DMODEL];
__device__ __nv_bfloat16 g_vh[(size_t)TOK*DMODEL], g_vl[(size_t)TOK*DMODEL];
// projected Q/K as split bf16 [tok, 1024]
__device__ __nv_bfloat16 g_Qph[(size_t)TOK*HDIM], g_Qpl[(size_t)TOK*HDIM];
__device__ __nv_bfloat16 g_Kph[(size_t)TOK*HDIM], g_Kpl[(size_t)TOK*HDIM];
// attention output as split bf16
__device__ __nv_bfloat16 g_aoh[(size_t)TOK*HDIM], g_aol[(size_t)TOK*HDIM];
// E = exp(scores) lower triangle, split bf16 [bh][q][k]
__device__ __nv_bfloat16 g_Ehi[(size_t)BB*NH*SS*SS];
__device__ __nv_bfloat16 g_Elo[(size_t)BB*NH*SS*SS];
// V * r transposed [bh][d=64][k=S], split bf16
__device__ __nv_bfloat16 g_Vrth[(size_t)BB*NH*64*SS];
__device__ __nv_bfloat16 g_Vrtl[(size_t)BB*NH*64*SS];
// split-bf16 transposed weights [N,K]
__device__ __nv_bfloat16 g_wqh[DMODEL*HDIM], g_wql[DMODEL*HDIM];
__device__ __nv_bfloat16 g_wkh[DMODEL*HDIM], g_wkl[DMODEL*HDIM];
__device__ __nv_bfloat16 g_wvh[DMODEL*HDIM], g_wvl[DMODEL*HDIM];
__device__ __nv_bfloat16 g_wvLh[DMODEL*HDIM], g_wvLl[DMODEL*HDIM];
__device__ __nv_bfloat16 g_woh[DMODEL*HDIM], g_wol[DMODEL*HDIM];

// ------------------- helpers ------------------------------------------------------
__device__ __forceinline__ uint32_t smem_u32(const void* p) {
    uint32_t a;
    asm("{ .reg .u64 t; cvta.to.shared.u64 t, %1; cvt.u32.u64 %0, t; }" : "=r"(a) : "l"(p));
    return a;
}
__device__ __forceinline__ void cpa16(uint32_t dst, const void* src) {
    asm volatile("cp.async.cg.shared.global [%0], [%1], 16;"
                 :: "r"(dst), "l"(__cvta_generic_to_global(src)));
}
#define CPA_COMMIT() asm volatile("cp.async.commit_group;")
#define CPA_WAIT1()  asm volatile("cp.async.wait_group 1;")
#define CPA_WAIT0()  asm volatile("cp.async.wait_group 0;")

#define LDSM4(r, a) \
    asm volatile("ldmatrix.sync.aligned.m8n8.x4.shared.b16 {%0,%1,%2,%3}, [%4];" \
        : "=r"((r)[0]), "=r"((r)[1]), "=r"((r)[2]), "=r"((r)[3]) : "r"(a))

#define MMA16816(c, a, b0, b1) \
    asm volatile("mma.sync.aligned.m16n8k16.row.col.f32.bf16.bf16.f32 " \
        "{%0,%1,%2,%3}, {%4,%5,%6,%7}, {%8,%9}, {%0,%1,%2,%3};" \
        : "+f"((c)[0]), "+f"((c)[1]), "+f"((c)[2]), "+f"((c)[3]) \
        : "r"((a)[0]), "r"((a)[1]), "r"((a)[2]), "r"((a)[3]), "r"(b0), "r"(b1))

// ------------------- prep kernels ------------------------------------------------
__global__ void beff_kernel(const float* __restrict__ Wb, const float* __restrict__ Ab,
                            const float* __restrict__ Bw, const float* __restrict__ Bb,
                            float* __restrict__ out)
{
    int j = blockIdx.x * 256 + threadIdx.x;
    float acc = Wb[j] + Bb[j];
#pragma unroll
    for (int r = 0; r < RK; r++) acc += Ab[r] * Bw[r*HDIM + j];
    out[j] = acc;
}

__global__ __launch_bounds__(256) void wprep_kernel(
    const float* __restrict__ W, const float* __restrict__ A, const float* __restrict__ Bw,
    __nv_bfloat16* __restrict__ hi, __nv_bfloat16* __restrict__ lo)
{
    __shared__ float t[32][33];
    int kb = blockIdx.x * 32, nb = blockIdx.y * 32;
    int x = threadIdx.x & 31, y = threadIdx.x >> 5;
#pragma unroll
    for (int i = y; i < 32; i += 8) {
        int k = kb + i, n = nb + x;
        float v = W ? W[(size_t)k*HDIM + n] : 0.f;
        if (A) {
#pragma unroll
            for (int r = 0; r < RK; r++) v += A[k*RK + r] * Bw[r*HDIM + n];
        }
        t[i][x] = v;
    }
    __syncthreads();
#pragma unroll
    for (int i = y; i < 32; i += 8) {
        int n = nb + i, k = kb + x;
        float v = t[x][i];
        __nv_bfloat16 h = __float2bfloat16(v);
        hi[(size_t)n*DMODEL + k] = h;
        lo[(size_t)n*DMODEL + k] = __float2bfloat16(v - __bfloat162float(h));
    }
}

__global__ void actconv_kernel(const float* __restrict__ X,
                               __nv_bfloat16* __restrict__ hi, __nv_bfloat16* __restrict__ lo)
{
    size_t i = ((size_t)blockIdx.x * 256 + threadIdx.x) * 4;
    float4 v = *(const float4*)&X[i];
    __nv_bfloat16 h0 = __float2bfloat16(v.x), h1 = __float2bfloat16(v.y);
    __nv_bfloat16 h2 = __float2bfloat16(v.z), h3 = __float2bfloat16(v.w);
    __nv_bfloat162 ph0 = {h0, h1}, ph1 = {h2, h3};
    __nv_bfloat162 pl0 = {__float2bfloat16(v.x - __bfloat162float(h0)),
                          __float2bfloat16(v.y - __bfloat162float(h1))};
    __nv_bfloat162 pl1 = {__float2bfloat16(v.z - __bfloat162float(h2)),
                          __float2bfloat16(v.w - __bfloat162float(h3))};
    *(__nv_bfloat162*)&hi[i]   = ph0;  *(__nv_bfloat162*)&hi[i+2] = ph1;
    *(__nv_bfloat162*)&lo[i]   = pl0;  *(__nv_bfloat162*)&lo[i+2] = pl1;
}

__global__ void zero_kernel(float* p) { p[blockIdx.x * 256 + threadIdx.x] = 0.f; }

// ------------------- mma.sync split-bf16 GEMM ------------------------------------
static constexpr int STAGE_BYTES = 40960;
static constexpr int GEMM_SMEM   = 2 * STAGE_BYTES;

__global__ __launch_bounds__(256, 1)
void gemm_mma(const __nv_bfloat16* __restrict__ A1h, const __nv_bfloat16* __restrict__ A1l,
              const __nv_bfloat16* __restrict__ B1h, const __nv_bfloat16* __restrict__ B1l,
              const __nv_bfloat16* __restrict__ A2h, const __nv_bfloat16* __restrict__ A2l,
              const __nv_bfloat16* __restrict__ B2h, const __nv_bfloat16* __restrict__ B2l,
              const float* __restrict__ bias, float* __restrict__ outF,
              __nv_bfloat16* __restrict__ outH, __nv_bfloat16* __restrict__ outL, int nchunks)
{
    extern __shared__ char smem[];
    const uint32_t sb = smem_u32(smem);
    const int tid  = threadIdx.x;
    const int lane = tid & 31;
    const int warp = tid >> 5;
    const int wm = warp >> 2, wn = warp & 3;
    const int m0 = blockIdx.y * 128, n0 = blockIdx.x * 128;

    float acc[4][4][4];
#pragma unroll
    for (int i = 0; i < 4; i++)
#pragma unroll
        for (int j = 0; j < 4; j++)
#pragma unroll
            for (int k = 0; k < 4; k++) acc[i][j][k] = 0.f;

    auto load_stage = [&](int st, int chunk) {
        int seg = chunk >> 5;
        int k0  = (chunk & 31) * 32;
        const __nv_bfloat16* tp[4] = {seg ? A2h : A1h, seg ? A2l : A1l,
                                      seg ? B2h : B1h, seg ? B2l : B1l};
        uint32_t sbase = sb + st * STAGE_BYTES;
#pragma unroll
        for (int i = 0; i < 8; i++) {
            const int t = i >> 1;
            int j = (i & 1) ? tid + 256 : tid;
            int row = j >> 2, sg = j & 3;
            int r0 = (t < 2) ? m0 : n0;
            cpa16(sbase + t * 10240 + row * 80 + sg * 16,
                  tp[t] + (size_t)(r0 + row) * 1024 + k0 + sg * 8);
        }
    };

    auto compute_stage = [&](int st) {
        uint32_t ab = sb + st * STAGE_BYTES;
#pragma unroll
        for (int kk = 0; kk < 2; kk++) {
            uint32_t ah[4][4], al[4][4], bh[4][2], bl[4][2];
            uint32_t aoff = (uint32_t)(wm*64 + (lane & 15)) * 80
                          + (uint32_t)(kk*16 + (lane >> 4) * 8) * 2;
#pragma unroll
            for (int mt = 0; mt < 4; mt++) {
                LDSM4(ah[mt], ab + aoff + mt * (16*80));
                LDSM4(al[mt], ab + 10240 + aoff + mt * (16*80));
            }
            uint32_t boff = (uint32_t)(wn*32 + (lane & 7) + ((lane >> 4) << 3)) * 80
                          + (uint32_t)(kk*16 + ((lane >> 3) & 1) * 8) * 2;
            {
                uint32_t t0[4], t1[4];
                LDSM4(t0, ab + 20480 + boff);
                LDSM4(t1, ab + 20480 + boff + 16*80);
                bh[0][0]=t0[0]; bh[0][1]=t0[1]; bh[1][0]=t0[2]; bh[1][1]=t0[3];
                bh[2][0]=t1[0]; bh[2][1]=t1[1]; bh[3][0]=t1[2]; bh[3][1]=t1[3];
                LDSM4(t0, ab + 30720 + boff);
                LDSM4(t1, ab + 30720 + boff + 16*80);
                bl[0][0]=t0[0]; bl[0][1]=t0[1]; bl[1][0]=t0[2]; bl[1][1]=t0[3];
                bl[2][0]=t1[0]; bl[2][1]=t1[1]; bl[3][0]=t1[2]; bl[3][1]=t1[3];
            }
#pragma unroll
            for (int mt = 0; mt < 4; mt++)
#pragma unroll
                for (int nt = 0; nt < 4; nt++) {
                    MMA16816(acc[mt][nt], ah[mt], bh[nt][0], bh[nt][1]);
                    MMA16816(acc[mt][nt], ah[mt], bl[nt][0], bl[nt][1]);
                    MMA16816(acc[mt][nt], al[mt], bh[nt][0], bh[nt][1]);
                }
        }
    };

    load_stage(0, 0);
    CPA_COMMIT();
    if (nchunks > 1) load_stage(1, 1);
    CPA_COMMIT();

    for (int c = 0; c < nchunks; c++) {
        CPA_WAIT1();
        __syncthreads();
        compute_stage(c & 1);
        __syncthreads();
        if (c + 2 < nchunks) load_stage(c & 1, c + 2);
        CPA_COMMIT();
    }

    int r_ = lane >> 2, c_ = (lane & 3) * 2;
#pragma unroll
    for (int mt = 0; mt < 4; mt++)
#pragma unroll
        for (int nt = 0; nt < 4; nt++) {
            int row = m0 + wm*64 + mt*16 + r_;
            int col = n0 + wn*32 + nt*8 + c_;
            float b0 = bias[col], b1 = bias[col + 1];
            float v00 = acc[mt][nt][0] + b0, v01 = acc[mt][nt][1] + b1;
            float v10 = acc[mt][nt][2] + b0, v11 = acc[mt][nt][3] + b1;
            if (outF) {
                *(float2*)&outF[(size_t)row * 1024 + col] = {v00, v01};
                *(float2*)&outF[(size_t)(row + 8) * 1024 + col] = {v10, v11};
            } else {
                __nv_bfloat16 h00 = __float2bfloat16(v00), h01 = __float2bfloat16(v01);
                __nv_bfloat16 h10 = __float2bfloat16(v10), h11 = __float2bfloat16(v11);
                __nv_bfloat162 hp0 = {h00, h01}, hp1 = {h10, h11};
                __nv_bfloat162 lp0 = {__float2bfloat16(v00 - __bfloat162float(h00)),
                                      __float2bfloat16(v01 - __bfloat162float(h01))};
                __nv_bfloat162 lp1 = {__float2bfloat16(v10 - __bfloat162float(h10)),
                                      __float2bfloat16(v11 - __bfloat162float(h11))};
                *(__nv_bfloat162*)&outH[(size_t)row * 1024 + col] = hp0;
                *(__nv_bfloat162*)&outH[(size_t)(row + 8) * 1024 + col] = hp1;
                *(__nv_bfloat162*)&outL[(size_t)row * 1024 + col] = lp0;
                *(__nv_bfloat162*)&outL[(size_t)(row + 8) * 1024 + col] = lp1;
            }
        }
}

// ------------------- pass 1 (mma): E = exp(QK^T) masked, column sums -------------
// grid (kt=16, qt=16, bh=64); lower-triangle tiles only. Tile 128q x 128k, D=64.
static constexpr int A1_PITCH = 144;                     // 64 bf16 + 16B pad
static constexpr int A1_TILE  = 128 * A1_PITCH;          // 18432
static constexpr int A1_SMEM  = 4 * A1_TILE;             // Qh Ql Kh Kl

__global__ __launch_bounds__(256, 1) void attn1_mma()
{
    extern __shared__ char smem[];
    int kt = blockIdx.x, qt = blockIdx.y, bh = blockIdx.z;
    if (qt < kt) return;
    const uint32_t sb = smem_u32(smem);
    int b = bh >> 4, h = bh & 15;
    int q0 = qt * 128, k0 = kt * 128;
    int tid = threadIdx.x, lane = tid & 31, warp = tid >> 5;
    int wm = warp >> 2, wn = warp & 3;

    {
        const __nv_bfloat16* tp[4] = {g_Qph, g_Qpl, g_Kph, g_Kpl};
#pragma unroll
        for (int t = 0; t < 4; t++) {
            int r0 = (t < 2) ? q0 : k0;
#pragma unroll
            for (int i = 0; i < 4; i++) {
                int idx = tid + i * 256;
                int row = idx >> 3, sg = idx & 7;
                cpa16(sb + t * A1_TILE + row * A1_PITCH + sg * 16,
                      tp[t] + (size_t)(b*SS + r0 + row) * 1024 + h*64 + sg * 8);
            }
        }
    }
    CPA_COMMIT(); CPA_WAIT0();
    __syncthreads();

    float acc[4][4][4];
#pragma unroll
    for (int i = 0; i < 4; i++)
#pragma unroll
        for (int j = 0; j < 4; j++)
#pragma unroll
            for (int k = 0; k < 4; k++) acc[i][j][k] = 0.f;

#pragma unroll
    for (int kk = 0; kk < 4; kk++) {     // 4 ksteps of d=16
        uint32_t ah[4][4], al[4][4], bhf[4][2], blf[4][2];
        uint32_t aoff = (uint32_t)(wm*64 + (lane & 15)) * A1_PITCH
                      + (uint32_t)(kk*16 + (lane >> 4) * 8) * 2;
#pragma unroll
        for (int mt = 0; mt < 4; mt++) {
            LDSM4(ah[mt], sb + aoff + mt * (16*A1_PITCH));
            LDSM4(al[mt], sb + A1_TILE + aoff + mt * (16*A1_PITCH));
        }
        uint32_t boff = (uint32_t)(wn*32 + (lane & 7) + ((lane >> 4) << 3)) * A1_PITCH
                      + (uint32_t)(kk*16 + ((lane >> 3) & 1) * 8) * 2;
        {
            uint32_t t0[4], t1[4];
            LDSM4(t0, sb + 2*A1_TILE + boff);
            LDSM4(t1, sb + 2*A1_TILE + boff + 16*A1_PITCH);
            bhf[0][0]=t0[0]; bhf[0][1]=t0[1]; bhf[1][0]=t0[2]; bhf[1][1]=t0[3];
            bhf[2][0]=t1[0]; bhf[2][1]=t1[1]; bhf[3][0]=t1[2]; bhf[3][1]=t1[3];
            LDSM4(t0, sb + 3*A1_TILE + boff);
            LDSM4(t1, sb + 3*A1_TILE + boff + 16*A1_PITCH);
            blf[0][0]=t0[0]; blf[0][1]=t0[1]; blf[1][0]=t0[2]; blf[1][1]=t0[3];
            blf[2][0]=t1[0]; blf[2][1]=t1[1]; blf[3][0]=t1[2]; blf[3][1]=t1[3];
        }
#pragma unroll
        for (int mt = 0; mt < 4; mt++)
#pragma unroll
            for (int nt = 0; nt < 4; nt++) {
                MMA16816(acc[mt][nt], ah[mt], bhf[nt][0], bhf[nt][1]);
                MMA16816(acc[mt][nt], ah[mt], blf[nt][0], blf[nt][1]);
                MMA16816(acc[mt][nt], al[mt], bhf[nt][0], bhf[nt][1]);
            }
    }

    // epilogue: exp + mask + store Ehi/Elo + column sums
    __syncthreads();
    float* cs = (float*)smem;
    if (tid < 128) cs[tid] = 0.f;
    __syncthreads();

    const bool diag = (qt == kt);
    int r_ = lane >> 2, c_ = (lane & 3) * 2;
    float cs0[4] = {0,0,0,0}, cs1[4] = {0,0,0,0};
#pragma unroll
    for (int mt = 0; mt < 4; mt++) {
        int qb = q0 + wm*64 + mt*16;
#pragma unroll
        for (int nt = 0; nt < 4; nt++) {
            int k = k0 + wn*32 + nt*8 + c_;
            float e00 = __expf(acc[mt][nt][0]);
            float e01 = __expf(acc[mt][nt][1]);
            float e10 = __expf(acc[mt][nt][2]);
            float e11 = __expf(acc[mt][nt][3]);
            int qr0 = qb + r_, qr1 = qb + r_ + 8;
            if (diag) {
                if (qr0 < k)     e00 = 0.f;
                if (qr0 < k + 1) e01 = 0.f;
                if (qr1 < k)     e10 = 0.f;
                if (qr1 < k + 1) e11 = 0.f;
            }
            cs0[nt] += e00 + e10;
            cs1[nt] += e01 + e11;
            __nv_bfloat16 h00 = __float2bfloat16(e00), h01 = __float2bfloat16(e01);
            __nv_bfloat16 h10 = __float2bfloat16(e10), h11 = __float2bfloat16(e11);
            __nv_bfloat162 hp0 = {h00, h01}, hp1 = {h10, h11};
            __nv_bfloat162 lp0 = {__float2bfloat16(e00 - __bfloat162float(h00)),
                                  __float2bfloat16(e01 - __bfloat162float(h01))};
            __nv_bfloat162 lp1 = {__float2bfloat16(e10 - __bfloat162float(h10)),
                                  __float2bfloat16(e11 - __bfloat162float(h11))};
            size_t b0i = ((size_t)bh*SS + qr0) * SS + k;
            size_t b1i = ((size_t)bh*SS + qr1) * SS + k;
            *(__nv_bfloat162*)&g_Ehi[b0i] = hp0;  *(__nv_bfloat162*)&g_Elo[b0i] = lp0;
            *(__nv_bfloat162*)&g_Ehi[b1i] = hp1;  *(__nv_bfloat162*)&g_Elo[b1i] = lp1;
        }
    }
#pragma unroll
    for (int nt = 0; nt < 4; nt++) {
        atomicAdd(&cs[wn*32 + nt*8 + c_],     cs0[nt]);
        atomicAdd(&cs[wn*32 + nt*8 + c_ + 1], cs1[nt]);
    }
    __syncthreads();
    if (tid < 128)
        atomicAdd(&g_colsum[(size_t)bh*SS + k0 + tid], cs[tid]);
}

// ------------------- Vrt prep: Vrt[bh][d][k] = V[b,k,h*64+d] / (8*colsum) --------
__global__ __launch_bounds__(256) void vrt_kernel()
{
    __shared__ float t[32][33];
    int kt = blockIdx.x, dt = blockIdx.y, bh = blockIdx.z;
    int b = bh >> 4, h = bh & 15;
    int k0 = kt * 32, d0 = dt * 32;
    int x = threadIdx.x & 31, y = threadIdx.x >> 5;
#pragma unroll
    for (int i = y; i < 32; i += 8) {
        int k = k0 + i;
        float r = 1.0f / (g_colsum[(size_t)bh*SS + k] * 8.0f);
        t[i][x] = g_V[(size_t)(b*SS + k) * HDIM + h*64 + d0 + x] * r;
    }
    __syncthreads();
#pragma unroll
    for (int i = y; i < 32; i += 8) {
        int d = d0 + i, k = k0 + x;
        float v = t[x][i];
        __nv_bfloat16 hh = __float2bfloat16(v);
        size_t idx = ((size_t)bh*64 + d) * SS + k;
        g_Vrth[idx] = hh;
        g_Vrtl[idx] = __float2bfloat16(v - __bfloat162float(hh));
    }
}

// ------------------- pass 2 (mma): attO = E @ Vrt^T ------------------------------
// grid (qt=16, bh=64). Tile 128q x 64d, contraction over k in 64-chunks, 2-stage.
static constexpr int A2_PITCH = 144;
static constexpr int A2_ATILE = 128 * A2_PITCH;    // 18432 (per hi/lo)
static constexpr int A2_BTILE = 64 * A2_PITCH;     // 9216
static constexpr int A2_STAGE = 2*A2_ATILE + 2*A2_BTILE;   // 55296
static constexpr int A2_SMEM  = 2 * A2_STAGE;              // 110592

__global__ __launch_bounds__(256, 1) void attn2_mma()
{
    extern __shared__ char smem[];
    const uint32_t sb = smem_u32(smem);
    int qt = blockIdx.x, bh = blockIdx.y;
    int b = bh >> 4, h = bh & 15;
    int q0 = qt * 128;
    int tid = threadIdx.x, lane = tid & 31, warp = tid >> 5;
    int wm = warp >> 1, wn = warp & 1;
    int nch = 2 * qt + 2;

    float acc[2][4][4];
#pragma unroll
    for (int i = 0; i < 2; i++)
#pragma unroll
        for (int j = 0; j < 4; j++)
#pragma unroll
            for (int k = 0; k < 4; k++) acc[i][j][k] = 0.f;

    auto load_stage = [&](int st, int c) {
        int k0 = c * 64;
        uint32_t sbase = sb + st * A2_STAGE;
        // E tiles: 128 rows x 8 chunks each, hi & lo
#pragma unroll
        for (int i = 0; i < 4; i++) {
            int idx = tid + i * 256;
            int row = idx >> 3, sg = idx & 7;
            size_t gi = ((size_t)bh*SS + q0 + row) * SS + k0 + sg * 8;
            cpa16(sbase + row * A2_PITCH + sg * 16, &g_Ehi[gi]);
            cpa16(sbase + A2_ATILE + row * A2_PITCH + sg * 16, &g_Elo[gi]);
        }
        // Vrt tiles: 64 rows x 8 chunks, hi & lo
#pragma unroll
        for (int i = 0; i < 2; i++) {
            int idx = tid + i * 256;
            int row = idx >> 3, sg = idx & 7;
            size_t gi = ((size_t)bh*64 + row) * SS + k0 + sg * 8;
            cpa16(sbase + 2*A2_ATILE + row * A2_PITCH + sg * 16, &g_Vrth[gi]);
            cpa16(sbase + 2*A2_ATILE + A2_BTILE + row * A2_PITCH + sg * 16, &g_Vrtl[gi]);
        }
    };

    auto compute_stage = [&](int st) {
        uint32_t ab = sb + st * A2_STAGE;
#pragma unroll
        for (int kk = 0; kk < 4; kk++) {
            uint32_t ah[2][4], al[2][4], bhf[4][2], blf[4][2];
            uint32_t aoff = (uint32_t)(wm*32 + (lane & 15)) * A2_PITCH
                          + (uint32_t)(kk*16 + (lane >> 4) * 8) * 2;
#pragma unroll
            for (int mt = 0; mt < 2; mt++) {
                LDSM4(ah[mt], ab + aoff + mt * (16*A2_PITCH));
                LDSM4(al[mt], ab + A2_ATILE + aoff + mt * (16*A2_PITCH));
            }
            uint32_t boff = (uint32_t)(wn*32 + (lane & 7) + ((lane >> 4) << 3)) * A2_PITCH
                          + (uint32_t)(kk*16 + ((lane >> 3) & 1) * 8) * 2;
            {
                uint32_t t0[4], t1[4];
                LDSM4(t0, ab + 2*A2_ATILE + boff);
                LDSM4(t1, ab + 2*A2_ATILE + boff + 16*A2_PITCH);
                bhf[0][0]=t0[0]; bhf[0][1]=t0[1]; bhf[1][0]=t0[2]; bhf[1][1]=t0[3];
                bhf[2][0]=t1[0]; bhf[2][1]=t1[1]; bhf[3][0]=t1[2]; bhf[3][1]=t1[3];
                LDSM4(t0, ab + 2*A2_ATILE + A2_BTILE + boff);
                LDSM4(t1, ab + 2*A2_ATILE + A2_BTILE + boff + 16*A2_PITCH);
                blf[0][0]=t0[0]; blf[0][1]=t0[1]; blf[1][0]=t0[2]; blf[1][1]=t0[3];
                blf[2][0]=t1[0]; blf[2][1]=t1[1]; blf[3][0]=t1[2]; blf[3][1]=t1[3];
            }
#pragma unroll
            for (int mt = 0; mt < 2; mt++)
#pragma unroll
                for (int nt = 0; nt < 4; nt++) {
                    MMA16816(acc[mt][nt], ah[mt], bhf[nt][0], bhf[nt][1]);
                    MMA16816(acc[mt][nt], ah[mt], blf[nt][0], blf[nt][1]);
                    MMA16816(acc[mt][nt], al[mt], bhf[nt][0], bhf[nt][1]);
                }
        }
    };

    load_stage(0, 0);
    CPA_COMMIT();
    load_stage(1, 1);
    CPA_COMMIT();

    for (int c = 0; c < nch; c++) {
        CPA_WAIT1();
        __syncthreads();
        compute_stage(c & 1);
        __syncthreads();
        if (c + 2 < nch) load_stage(c & 1, c + 2);
        CPA_COMMIT();
    }

    int r_ = lane >> 2, c_ = (lane & 3) * 2;
#pragma unroll
    for (int mt = 0; mt < 2; mt++)
#pragma unroll
        for (int nt = 0; nt < 4; nt++) {
            int q  = q0 + wm*32 + mt*16 + r_;
            int d  = wn*32 + nt*8 + c_;
            float v00 = acc[mt][nt][0], v01 = acc[mt][nt][1];
            float v10 = acc[mt][nt][2], v11 = acc[mt][nt][3];
            size_t i0 = (size_t)(b*SS + q) * HDIM + h*64 + d;
            size_t i1 = (size_t)(b*SS + q + 8) * HDIM + h*64 + d;
            __nv_bfloat16 h00 = __float2bfloat16(v00), h01 = __float2bfloat16(v01);
            __nv_bfloat16 h10 = __float2bfloat16(v10), h11 = __float2bfloat16(v11);
            __nv_bfloat162 hp0 = {h00, h01}, hp1 = {h10, h11};
            __nv_bfloat162 lp0 = {__float2bfloat16(v00 - __bfloat162float(h00)),
                                  __float2bfloat16(v01 - __bfloat162float(h01))};
            __nv_bfloat162 lp1 = {__float2bfloat16(v10 - __bfloat162float(h10)),
                                  __float2bfloat16(v11 - __bfloat162float(h11))};
            *(__nv_bfloat162*)&g_aoh[i0] = hp0;  *(__nv_bfloat162*)&g_aol[i0] = lp0;
            *(__nv_bfloat162*)&g_aoh[i1] = hp1;  *(__nv_bfloat162*)&g_aol[i1] = lp1;
        }
}

// ------------------- launch ------------------------------------------------------
extern "C" void kernel_launch(void* const* d_in, const int* in_sizes, int n_in,
                              void* d_out, int out_size)
{
    const float* queries = (const float*)d_in[0];
    const float* keys    = (const float*)d_in[1];
    const float* values  = (const float*)d_in[2];
    const float* Wq_w = (const float*)d_in[3];  const float* Wq_b = (const float*)d_in[4];
    const float* Wk_w = (const float*)d_in[5];  const float* Wk_b = (const float*)d_in[6];
    const float* Wv_w = (const float*)d_in[7];  const float* Wv_b = (const float*)d_in[8];
    const float* Aq_w = (const float*)d_in[9];  const float* Aq_b = (const float*)d_in[10];
    const float* Bq_w = (const float*)d_in[11]; const float* Bq_b = (const float*)d_in[12];
    const float* Ak_w = (const float*)d_in[13]; const float* Ak_b = (const float*)d_in[14];
    const float* Bk_w = (const float*)d_in[15]; const float* Bk_b = (const float*)d_in[16];
    const float* Av_w = (const float*)d_in[17]; const float* Av_b = (const float*)d_in[18];
    const float* Bv_w = (const float*)d_in[19]; const float* Bv_b = (const float*)d_in[20];
    const float* Wo_w = (const float*)d_in[21]; const float* Wo_b = (const float*)d_in[22];
    float* out = (float*)d_out;

    cudaFuncSetAttribute(gemm_mma, cudaFuncAttributeMaxDynamicSharedMemorySize, GEMM_SMEM);
    cudaFuncSetAttribute(attn1_mma, cudaFuncAttributeMaxDynamicSharedMemorySize, A1_SMEM);
    cudaFuncSetAttribute(attn2_mma, cudaFuncAttributeMaxDynamicSharedMemorySize, A2_SMEM);

    void *pbeq, *pbek, *pbev, *pV, *pcs;
    void *pqh, *pql, *pkh, *pkl, *pvh, *pvl, *paoh, *paol;
    void *pQph, *pQpl, *pKph, *pKpl;
    void *pwqh, *pwql, *pwkh, *pwkl, *pwvh, *pwvl, *pwvLh, *pwvLl, *pwoh, *pwol;
    cudaGetSymbolAddress(&pbeq, g_beq); cudaGetSymbolAddress(&pbek, g_bek);
    cudaGetSymbolAddress(&pbev, g_bev); cudaGetSymbolAddress(&pV, g_V);
    cudaGetSymbolAddress(&pcs, g_colsum);
    cudaGetSymbolAddress(&pqh, g_qh); cudaGetSymbolAddress(&pql, g_ql);
    cudaGetSymbolAddress(&pkh, g_kh); cudaGetSymbolAddress(&pkl, g_kl);
    cudaGetSymbolAddress(&pvh, g_vh); cudaGetSymbolAddress(&pvl, g_vl);
    cudaGetSymbolAddress(&paoh, g_aoh); cudaGetSymbolAddress(&paol, g_aol);
    cudaGetSymbolAddress(&pQph, g_Qph); cudaGetSymbolAddress(&pQpl, g_Qpl);
    cudaGetSymbolAddress(&pKph, g_Kph); cudaGetSymbolAddress(&pKpl, g_Kpl);
    cudaGetSymbolAddress(&pwqh, g_wqh); cudaGetSymbolAddress(&pwql, g_wql);
    cudaGetSymbolAddress(&pwkh, g_wkh); cudaGetSymbolAddress(&pwkl, g_wkl);
    cudaGetSymbolAddress(&pwvh, g_wvh); cudaGetSymbolAddress(&pwvl, g_wvl);
    cudaGetSymbolAddress(&pwvLh, g_wvLh); cudaGetSymbolAddress(&pwvLl, g_wvLl);
    cudaGetSymbolAddress(&pwoh, g_woh); cudaGetSymbolAddress(&pwol, g_wol);

    int actblocks = (TOK * DMODEL / 4) / 256;
    actconv_kernel<<<actblocks, 256>>>(queries, (__nv_bfloat16*)pqh, (__nv_bfloat16*)pql);
    actconv_kernel<<<actblocks, 256>>>(keys,    (__nv_bfloat16*)pkh, (__nv_bfloat16*)pkl);
    actconv_kernel<<<actblocks, 256>>>(values,  (__nv_bfloat16*)pvh, (__nv_bfloat16*)pvl);

    dim3 wgrid(DMODEL/32, HDIM/32);
    wprep_kernel<<<wgrid, 256>>>(Wq_w, Aq_w, Bq_w, (__nv_bfloat16*)pwqh, (__nv_bfloat16*)pwql);
    wprep_kernel<<<wgrid, 256>>>(Wk_w, Ak_w, Bk_w, (__nv_bfloat16*)pwkh, (__nv_bfloat16*)pwkl);
    wprep_kernel<<<wgrid, 256>>>(Wv_w, nullptr, nullptr, (__nv_bfloat16*)pwvh, (__nv_bfloat16*)pwvl);
    wprep_kernel<<<wgrid, 256>>>(nullptr, Av_w, Bv_w, (__nv_bfloat16*)pwvLh, (__nv_bfloat16*)pwvLl);
    wprep_kernel<<<wgrid, 256>>>(Wo_w, nullptr, nullptr, (__nv_bfloat16*)pwoh, (__nv_bfloat16*)pwol);

    beff_kernel<<<HDIM/256, 256>>>(Wq_b, Aq_b, Bq_w, Bq_b, (float*)pbeq);
    beff_kernel<<<HDIM/256, 256>>>(Wk_b, Ak_b, Bk_w, Bk_b, (float*)pbek);
    beff_kernel<<<HDIM/256, 256>>>(Wv_b, Av_b, Bv_w, Bv_b, (float*)pbev);

    zero_kernel<<<(BB*NH*SS)/256, 256>>>((float*)pcs);

    dim3 ggrid(HDIM/128, TOK/128);
    gemm_mma<<<ggrid, 256, GEMM_SMEM>>>(
        (const __nv_bfloat16*)pqh, (const __nv_bfloat16*)pql,
        (const __nv_bfloat16*)pwqh, (const __nv_bfloat16*)pwql,
        nullptr, nullptr, nullptr, nullptr,
        (const float*)pbeq, nullptr,
        (__nv_bfloat16*)pQph, (__nv_bfloat16*)pQpl, 32);
    gemm_mma<<<ggrid, 256, GEMM_SMEM>>>(
        (const __nv_bfloat16*)pkh, (const __nv_bfloat16*)pkl,
        (const __nv_bfloat16*)pwkh, (const __nv_bfloat16*)pwkl,
        nullptr, nullptr, nullptr, nullptr,
        (const float*)pbek, nullptr,
        (__nv_bfloat16*)pKph, (__nv_bfloat16*)pKpl, 32);
    gemm_mma<<<ggrid, 256, GEMM_SMEM>>>(
        (const __nv_bfloat16*)pvh, (const __nv_bfloat16*)pvl,
        (const __nv_bfloat16*)pwvh, (const __nv_bfloat16*)pwvl,
        (const __nv_bfloat16*)pkh, (const __nv_bfloat16*)pkl,
        (const __nv_bfloat16*)pwvLh, (const __nv_bfloat16*)pwvLl,
        (const float*)pbev, (float*)pV, nullptr, nullptr, 64);

    attn1_mma<<<dim3(16, 16, BB*NH), 256, A1_SMEM>>>();
    vrt_kernel<<<dim3(SS/32, 2, BB*NH), 256>>>();
    attn2_mma<<<dim3(16, BB*NH), 256, A2_SMEM>>>();

    gemm_mma<<<ggrid, 256, GEMM_SMEM>>>(
        (const __nv_bfloat16*)paoh, (const __nv_bfloat16*)paol,
        (const __nv_bfloat16*)pwoh, (const __nv_bfloat16*)pwol,
        nullptr, nullptr, nullptr, nullptr,
        Wo_b, out, nullptr, nullptr, 32);
}

// round 5
// speedup vs baseline: 2.2447x; 1.1540x over previous
#include <cuda_runtime.h>
#include <cuda_bf16.h>
#include <math.h>
#include <stdint.h>

#define BB     4
#define SS     2048
#define DMODEL 1024
#define NH     16
#define HD     64
#define HDIM   1024
#define RK     8
#define TOK    (BB*SS)   // 8192

// ------------------- device scratch (static; allocation-free) -------------------
__device__ float g_beq[HDIM];
__device__ float g_bek[HDIM];
__device__ float g_bev[HDIM];
__device__ float g_V[(size_t)TOK*HDIM];            // projected V (fp32)
__device__ float g_colsum[(size_t)BB*NH*SS];       // per-(head,k) exp column sums
__device__ float g_KA[(size_t)TOK*RK];             // keys @ Av (rank-8 LoRA)

// split-bf16 input activations [M,K] K-major
__device__ __nv_bfloat16 g_qh[(size_t)TOK*DMODEL], g_ql[(size_t)TOK*DMODEL];
__device__ __nv_bfloat16 g_kh[(size_t)TOK*DMODEL], g_kl[(size_t)TOK*DMODEL];
__device__ __nv_bfloat16 g_vh[(size_t)TOK*DMODEL], g_vl[(size_t)TOK*DMODEL];
// projected Q/K as split bf16 [tok, 1024]
__device__ __nv_bfloat16 g_Qph[(size_t)TOK*HDIM], g_Qpl[(size_t)TOK*HDIM];
__device__ __nv_bfloat16 g_Kph[(size_t)TOK*HDIM], g_Kpl[(size_t)TOK*HDIM];
// attention output as split bf16
__device__ __nv_bfloat16 g_aoh[(size_t)TOK*HDIM], g_aol[(size_t)TOK*HDIM];
// E = exp(scores) lower triangle, split bf16 [bh][q][k]
__device__ __nv_bfloat16 g_Ehi[(size_t)BB*NH*SS*SS];
__device__ __nv_bfloat16 g_Elo[(size_t)BB*NH*SS*SS];
// V * r transposed [bh][d=64][k=S], split bf16
__device__ __nv_bfloat16 g_Vrth[(size_t)BB*NH*64*SS];
__device__ __nv_bfloat16 g_Vrtl[(size_t)BB*NH*64*SS];
// split-bf16 transposed weights [N,K]
__device__ __nv_bfloat16 g_wqh[DMODEL*HDIM], g_wql[DMODEL*HDIM];
__device__ __nv_bfloat16 g_wkh[DMODEL*HDIM], g_wkl[DMODEL*HDIM];
__device__ __nv_bfloat16 g_wvh[DMODEL*HDIM], g_wvl[DMODEL*HDIM];
__device__ __nv_bfloat16 g_woh[DMODEL*HDIM], g_wol[DMODEL*HDIM];

// ------------------- helpers ------------------------------------------------------
__device__ __forceinline__ uint32_t smem_u32(const void* p) {
    uint32_t a;
    asm("{ .reg .u64 t; cvta.to.shared.u64 t, %1; cvt.u32.u64 %0, t; }" : "=r"(a) : "l"(p));
    return a;
}
__device__ __forceinline__ void cpa16(uint32_t dst, const void* src) {
    asm volatile("cp.async.cg.shared.global [%0], [%1], 16;"
                 :: "r"(dst), "l"(__cvta_generic_to_global(src)));
}
#define CPA_COMMIT() asm volatile("cp.async.commit_group;")
#define CPA_WAIT1()  asm volatile("cp.async.wait_group 1;")
#define CPA_WAIT0()  asm volatile("cp.async.wait_group 0;")

#define LDSM4(r, a) \
    asm volatile("ldmatrix.sync.aligned.m8n8.x4.shared.b16 {%0,%1,%2,%3}, [%4];" \
        : "=r"((r)[0]), "=r"((r)[1]), "=r"((r)[2]), "=r"((r)[3]) : "r"(a))

#define MMA16816(c, a, b0, b1) \
    asm volatile("mma.sync.aligned.m16n8k16.row.col.f32.bf16.bf16.f32 " \
        "{%0,%1,%2,%3}, {%4,%5,%6,%7}, {%8,%9}, {%0,%1,%2,%3};" \
        : "+f"((c)[0]), "+f"((c)[1]), "+f"((c)[2]), "+f"((c)[3]) \
        : "r"((a)[0]), "r"((a)[1]), "r"((a)[2]), "r"((a)[3]), "r"(b0), "r"(b1))

// ------------------- prep kernels ------------------------------------------------
__global__ void beff_kernel(const float* __restrict__ Wb, const float* __restrict__ Ab,
                            const float* __restrict__ Bw, const float* __restrict__ Bb,
                            float* __restrict__ out)
{
    int j = blockIdx.x * 256 + threadIdx.x;
    float acc = Wb[j] + Bb[j];
#pragma unroll
    for (int r = 0; r < RK; r++) acc += Ab[r] * Bw[r*HDIM + j];
    out[j] = acc;
}

__global__ __launch_bounds__(256) void wprep_kernel(
    const float* __restrict__ W, const float* __restrict__ A, const float* __restrict__ Bw,
    __nv_bfloat16* __restrict__ hi, __nv_bfloat16* __restrict__ lo)
{
    __shared__ float t[32][33];
    int kb = blockIdx.x * 32, nb = blockIdx.y * 32;
    int x = threadIdx.x & 31, y = threadIdx.x >> 5;
#pragma unroll
    for (int i = y; i < 32; i += 8) {
        int k = kb + i, n = nb + x;
        float v = W[(size_t)k*HDIM + n];
        if (A) {
#pragma unroll
            for (int r = 0; r < RK; r++) v += A[k*RK + r] * Bw[r*HDIM + n];
        }
        t[i][x] = v;
    }
    __syncthreads();
#pragma unroll
    for (int i = y; i < 32; i += 8) {
        int n = nb + i, k = kb + x;
        float v = t[x][i];
        __nv_bfloat16 h = __float2bfloat16(v);
        hi[(size_t)n*DMODEL + k] = h;
        lo[(size_t)n*DMODEL + k] = __float2bfloat16(v - __bfloat162float(h));
    }
}

__global__ void actconv_kernel(const float* __restrict__ X,
                               __nv_bfloat16* __restrict__ hi, __nv_bfloat16* __restrict__ lo)
{
    size_t i = ((size_t)blockIdx.x * 256 + threadIdx.x) * 4;
    float4 v = *(const float4*)&X[i];
    __nv_bfloat16 h0 = __float2bfloat16(v.x), h1 = __float2bfloat16(v.y);
    __nv_bfloat16 h2 = __float2bfloat16(v.z), h3 = __float2bfloat16(v.w);
    __nv_bfloat162 ph0 = {h0, h1}, ph1 = {h2, h3};
    __nv_bfloat162 pl0 = {__float2bfloat16(v.x - __bfloat162float(h0)),
                          __float2bfloat16(v.y - __bfloat162float(h1))};
    __nv_bfloat162 pl1 = {__float2bfloat16(v.z - __bfloat162float(h2)),
                          __float2bfloat16(v.w - __bfloat162float(h3))};
    *(__nv_bfloat162*)&hi[i]   = ph0;  *(__nv_bfloat162*)&hi[i+2] = ph1;
    *(__nv_bfloat162*)&lo[i]   = pl0;  *(__nv_bfloat162*)&lo[i+2] = pl1;
}

__global__ void zero_kernel(float* p) { p[blockIdx.x * 256 + threadIdx.x] = 0.f; }

// KA[tok, 8] = keys @ Av  (rank-8, fp32 exact). One warp per token row.
__global__ __launch_bounds__(256) void ka_kernel(const float* __restrict__ keys,
                                                 const float* __restrict__ Av,
                                                 float* __restrict__ KA)
{
    int row = blockIdx.x * 8 + (threadIdx.x >> 5);
    int lane = threadIdx.x & 31;
    float acc[RK];
#pragma unroll
    for (int r = 0; r < RK; r++) acc[r] = 0.f;
    const float* kr = keys + (size_t)row * DMODEL;
    for (int k = lane; k < DMODEL; k += 32) {
        float kv = kr[k];
#pragma unroll
        for (int r = 0; r < RK; r++) acc[r] += kv * Av[k*RK + r];
    }
#pragma unroll
    for (int r = 0; r < RK; r++) {
#pragma unroll
        for (int off = 16; off > 0; off >>= 1)
            acc[r] += __shfl_down_sync(0xffffffffu, acc[r], off);
    }
    if (lane == 0) {
#pragma unroll
        for (int r = 0; r < RK; r++) KA[(size_t)row*RK + r] = acc[r];
    }
}

// ------------------- mma.sync split-bf16 GEMM (K=1024, 32 chunks) ----------------
static constexpr int STAGE_BYTES = 40960;
static constexpr int GEMM_SMEM   = 2 * STAGE_BYTES;

__global__ __launch_bounds__(256, 2)
void gemm_mma(const __nv_bfloat16* __restrict__ Ah, const __nv_bfloat16* __restrict__ Al,
              const __nv_bfloat16* __restrict__ Bh, const __nv_bfloat16* __restrict__ Bl,
              const float* __restrict__ bias,
              const float* __restrict__ loraKA, const float* __restrict__ loraB,
              float* __restrict__ outF,
              __nv_bfloat16* __restrict__ outH, __nv_bfloat16* __restrict__ outL)
{
    extern __shared__ char smem[];
    const uint32_t sb = smem_u32(smem);
    const int tid  = threadIdx.x;
    const int lane = tid & 31;
    const int warp = tid >> 5;
    const int wm = warp >> 2, wn = warp & 3;
    const int m0 = blockIdx.y * 128, n0 = blockIdx.x * 128;

    float acc[4][4][4];
#pragma unroll
    for (int i = 0; i < 4; i++)
#pragma unroll
        for (int j = 0; j < 4; j++)
#pragma unroll
            for (int k = 0; k < 4; k++) acc[i][j][k] = 0.f;

    auto load_stage = [&](int st, int chunk) {
        int k0 = chunk * 32;
        const __nv_bfloat16* tp[4] = {Ah, Al, Bh, Bl};
        uint32_t sbase = sb + st * STAGE_BYTES;
#pragma unroll
        for (int i = 0; i < 8; i++) {
            const int t = i >> 1;
            int j = (i & 1) ? tid + 256 : tid;
            int row = j >> 2, sg = j & 3;
            int r0 = (t < 2) ? m0 : n0;
            cpa16(sbase + t * 10240 + row * 80 + sg * 16,
                  tp[t] + (size_t)(r0 + row) * 1024 + k0 + sg * 8);
        }
    };

    auto compute_stage = [&](int st) {
        uint32_t ab = sb + st * STAGE_BYTES;
#pragma unroll
        for (int kk = 0; kk < 2; kk++) {
            uint32_t ahr[4][4], alr[4][4], bh2[4][2], bl2[4][2];
            uint32_t aoff = (uint32_t)(wm*64 + (lane & 15)) * 80
                          + (uint32_t)(kk*16 + (lane >> 4) * 8) * 2;
#pragma unroll
            for (int mt = 0; mt < 4; mt++) {
                LDSM4(ahr[mt], ab + aoff + mt * (16*80));
                LDSM4(alr[mt], ab + 10240 + aoff + mt * (16*80));
            }
            uint32_t boff = (uint32_t)(wn*32 + (lane & 7) + ((lane >> 4) << 3)) * 80
                          + (uint32_t)(kk*16 + ((lane >> 3) & 1) * 8) * 2;
            {
                uint32_t t0[4], t1[4];
                LDSM4(t0, ab + 20480 + boff);
                LDSM4(t1, ab + 20480 + boff + 16*80);
                bh2[0][0]=t0[0]; bh2[0][1]=t0[1]; bh2[1][0]=t0[2]; bh2[1][1]=t0[3];
                bh2[2][0]=t1[0]; bh2[2][1]=t1[1]; bh2[3][0]=t1[2]; bh2[3][1]=t1[3];
                LDSM4(t0, ab + 30720 + boff);
                LDSM4(t1, ab + 30720 + boff + 16*80);
                bl2[0][0]=t0[0]; bl2[0][1]=t0[1]; bl2[1][0]=t0[2]; bl2[1][1]=t0[3];
                bl2[2][0]=t1[0]; bl2[2][1]=t1[1]; bl2[3][0]=t1[2]; bl2[3][1]=t1[3];
            }
#pragma unroll
            for (int mt = 0; mt < 4; mt++)
#pragma unroll
                for (int nt = 0; nt < 4; nt++) {
                    MMA16816(acc[mt][nt], ahr[mt], bh2[nt][0], bh2[nt][1]);
                    MMA16816(acc[mt][nt], ahr[mt], bl2[nt][0], bl2[nt][1]);
                    MMA16816(acc[mt][nt], alr[mt], bh2[nt][0], bh2[nt][1]);
                }
        }
    };

    load_stage(0, 0);
    CPA_COMMIT();
    load_stage(1, 1);
    CPA_COMMIT();

#pragma unroll 1
    for (int c = 0; c < 32; c++) {
        CPA_WAIT1();
        __syncthreads();
        compute_stage(c & 1);
        __syncthreads();
        if (c + 2 < 32) load_stage(c & 1, c + 2);
        CPA_COMMIT();
    }

    int r_ = lane >> 2, c_ = (lane & 3) * 2;
#pragma unroll
    for (int mt = 0; mt < 4; mt++) {
        int row = m0 + wm*64 + mt*16 + r_;
        float ka0[RK], ka1[RK];
        if (loraKA) {
#pragma unroll
            for (int r = 0; r < RK; r++) {
                ka0[r] = loraKA[(size_t)row*RK + r];
                ka1[r] = loraKA[(size_t)(row+8)*RK + r];
            }
        }
#pragma unroll
        for (int nt = 0; nt < 4; nt++) {
            int col = n0 + wn*32 + nt*8 + c_;
            float b0 = bias[col], b1 = bias[col + 1];
            float v00 = acc[mt][nt][0] + b0, v01 = acc[mt][nt][1] + b1;
            float v10 = acc[mt][nt][2] + b0, v11 = acc[mt][nt][3] + b1;
            if (loraKA) {
#pragma unroll
                for (int r = 0; r < RK; r++) {
                    float w0 = loraB[r*HDIM + col], w1 = loraB[r*HDIM + col + 1];
                    v00 += ka0[r] * w0;  v01 += ka0[r] * w1;
                    v10 += ka1[r] * w0;  v11 += ka1[r] * w1;
                }
            }
            if (outF) {
                *(float2*)&outF[(size_t)row * 1024 + col] = {v00, v01};
                *(float2*)&outF[(size_t)(row + 8) * 1024 + col] = {v10, v11};
            } else {
                __nv_bfloat16 h00 = __float2bfloat16(v00), h01 = __float2bfloat16(v01);
                __nv_bfloat16 h10 = __float2bfloat16(v10), h11 = __float2bfloat16(v11);
                __nv_bfloat162 hp0 = {h00, h01}, hp1 = {h10, h11};
                __nv_bfloat162 lp0 = {__float2bfloat16(v00 - __bfloat162float(h00)),
                                      __float2bfloat16(v01 - __bfloat162float(h01))};
                __nv_bfloat162 lp1 = {__float2bfloat16(v10 - __bfloat162float(h10)),
                                      __float2bfloat16(v11 - __bfloat162float(h11))};
                *(__nv_bfloat162*)&outH[(size_t)row * 1024 + col] = hp0;
                *(__nv_bfloat162*)&outH[(size_t)(row + 8) * 1024 + col] = hp1;
                *(__nv_bfloat162*)&outL[(size_t)row * 1024 + col] = lp0;
                *(__nv_bfloat162*)&outL[(size_t)(row + 8) * 1024 + col] = lp1;
            }
        }
    }
}

// ------------------- pass 1 (mma): E = exp(QK^T) masked, column sums -------------
static constexpr int A1_PITCH = 144;
static constexpr int A1_TILE  = 128 * A1_PITCH;          // 18432
static constexpr int A1_SMEM  = 4 * A1_TILE;             // 73728

__global__ __launch_bounds__(256, 2) void attn1_mma()
{
    extern __shared__ char smem[];
    int kt = blockIdx.x, qt = blockIdx.y, bh = blockIdx.z;
    if (qt < kt) return;
    const uint32_t sb = smem_u32(smem);
    int b = bh >> 4, h = bh & 15;
    int q0 = qt * 128, k0 = kt * 128;
    int tid = threadIdx.x, lane = tid & 31, warp = tid >> 5;
    int wm = warp >> 2, wn = warp & 3;

    {
        const __nv_bfloat16* tp[4] = {g_Qph, g_Qpl, g_Kph, g_Kpl};
#pragma unroll
        for (int t = 0; t < 4; t++) {
            int r0 = (t < 2) ? q0 : k0;
#pragma unroll
            for (int i = 0; i < 4; i++) {
                int idx = tid + i * 256;
                int row = idx >> 3, sg = idx & 7;
                cpa16(sb + t * A1_TILE + row * A1_PITCH + sg * 16,
                      tp[t] + (size_t)(b*SS + r0 + row) * 1024 + h*64 + sg * 8);
            }
        }
    }
    CPA_COMMIT(); CPA_WAIT0();
    __syncthreads();

    float acc[4][4][4];
#pragma unroll
    for (int i = 0; i < 4; i++)
#pragma unroll
        for (int j = 0; j < 4; j++)
#pragma unroll
            for (int k = 0; k < 4; k++) acc[i][j][k] = 0.f;

#pragma unroll
    for (int kk = 0; kk < 4; kk++) {
        uint32_t ahr[4][4], alr[4][4], bhf[4][2], blf[4][2];
        uint32_t aoff = (uint32_t)(wm*64 + (lane & 15)) * A1_PITCH
                      + (uint32_t)(kk*16 + (lane >> 4) * 8) * 2;
#pragma unroll
        for (int mt = 0; mt < 4; mt++) {
            LDSM4(ahr[mt], sb + aoff + mt * (16*A1_PITCH));
            LDSM4(alr[mt], sb + A1_TILE + aoff + mt * (16*A1_PITCH));
        }
        uint32_t boff = (uint32_t)(wn*32 + (lane & 7) + ((lane >> 4) << 3)) * A1_PITCH
                      + (uint32_t)(kk*16 + ((lane >> 3) & 1) * 8) * 2;
        {
            uint32_t t0[4], t1[4];
            LDSM4(t0, sb + 2*A1_TILE + boff);
            LDSM4(t1, sb + 2*A1_TILE + boff + 16*A1_PITCH);
            bhf[0][0]=t0[0]; bhf[0][1]=t0[1]; bhf[1][0]=t0[2]; bhf[1][1]=t0[3];
            bhf[2][0]=t1[0]; bhf[2][1]=t1[1]; bhf[3][0]=t1[2]; bhf[3][1]=t1[3];
            LDSM4(t0, sb + 3*A1_TILE + boff);
            LDSM4(t1, sb + 3*A1_TILE + boff + 16*A1_PITCH);
            blf[0][0]=t0[0]; blf[0][1]=t0[1]; blf[1][0]=t0[2]; blf[1][1]=t0[3];
            blf[2][0]=t1[0]; blf[2][1]=t1[1]; blf[3][0]=t1[2]; blf[3][1]=t1[3];
        }
#pragma unroll
        for (int mt = 0; mt < 4; mt++)
#pragma unroll
            for (int nt = 0; nt < 4; nt++) {
                MMA16816(acc[mt][nt], ahr[mt], bhf[nt][0], bhf[nt][1]);
                MMA16816(acc[mt][nt], ahr[mt], blf[nt][0], blf[nt][1]);
                MMA16816(acc[mt][nt], alr[mt], bhf[nt][0], bhf[nt][1]);
            }
    }

    __syncthreads();
    float* cs = (float*)smem;
    if (tid < 128) cs[tid] = 0.f;
    __syncthreads();

    const bool diag = (qt == kt);
    int r_ = lane >> 2, c_ = (lane & 3) * 2;
    float cs0[4] = {0,0,0,0}, cs1[4] = {0,0,0,0};
#pragma unroll
    for (int mt = 0; mt < 4; mt++) {
        int qb = q0 + wm*64 + mt*16;
#pragma unroll
        for (int nt = 0; nt < 4; nt++) {
            int k = k0 + wn*32 + nt*8 + c_;
            float e00 = __expf(acc[mt][nt][0]);
            float e01 = __expf(acc[mt][nt][1]);
            float e10 = __expf(acc[mt][nt][2]);
            float e11 = __expf(acc[mt][nt][3]);
            int qr0 = qb + r_, qr1 = qb + r_ + 8;
            if (diag) {
                if (qr0 < k)     e00 = 0.f;
                if (qr0 < k + 1) e01 = 0.f;
                if (qr1 < k)     e10 = 0.f;
                if (qr1 < k + 1) e11 = 0.f;
            }
            cs0[nt] += e00 + e10;
            cs1[nt] += e01 + e11;
            __nv_bfloat16 h00 = __float2bfloat16(e00), h01 = __float2bfloat16(e01);
            __nv_bfloat16 h10 = __float2bfloat16(e10), h11 = __float2bfloat16(e11);
            __nv_bfloat162 hp0 = {h00, h01}, hp1 = {h10, h11};
            __nv_bfloat162 lp0 = {__float2bfloat16(e00 - __bfloat162float(h00)),
                                  __float2bfloat16(e01 - __bfloat162float(h01))};
            __nv_bfloat162 lp1 = {__float2bfloat16(e10 - __bfloat162float(h10)),
                                  __float2bfloat16(e11 - __bfloat162float(h11))};
            size_t b0i = ((size_t)bh*SS + qr0) * SS + k;
            size_t b1i = ((size_t)bh*SS + qr1) * SS + k;
            *(__nv_bfloat162*)&g_Ehi[b0i] = hp0;  *(__nv_bfloat162*)&g_Elo[b0i] = lp0;
            *(__nv_bfloat162*)&g_Ehi[b1i] = hp1;  *(__nv_bfloat162*)&g_Elo[b1i] = lp1;
        }
    }
#pragma unroll
    for (int nt = 0; nt < 4; nt++) {
        atomicAdd(&cs[wn*32 + nt*8 + c_],     cs0[nt]);
        atomicAdd(&cs[wn*32 + nt*8 + c_ + 1], cs1[nt]);
    }
    __syncthreads();
    if (tid < 128)
        atomicAdd(&g_colsum[(size_t)bh*SS + k0 + tid], cs[tid]);
}

// ------------------- Vrt prep: Vrt[bh][d][k] = V[b,k,h*64+d] / (8*colsum) --------
__global__ __launch_bounds__(256) void vrt_kernel()
{
    __shared__ float t[32][33];
    int kt = blockIdx.x, dt = blockIdx.y, bh = blockIdx.z;
    int b = bh >> 4, h = bh & 15;
    int k0 = kt * 32, d0 = dt * 32;
    int x = threadIdx.x & 31, y = threadIdx.x >> 5;
#pragma unroll
    for (int i = y; i < 32; i += 8) {
        int k = k0 + i;
        float r = 1.0f / (g_colsum[(size_t)bh*SS + k] * 8.0f);
        t[i][x] = g_V[(size_t)(b*SS + k) * HDIM + h*64 + d0 + x] * r;
    }
    __syncthreads();
#pragma unroll
    for (int i = y; i < 32; i += 8) {
        int d = d0 + i, k = k0 + x;
        float v = t[x][i];
        __nv_bfloat16 hh = __float2bfloat16(v);
        size_t idx = ((size_t)bh*64 + d) * SS + k;
        g_Vrth[idx] = hh;
        g_Vrtl[idx] = __float2bfloat16(v - __bfloat162float(hh));
    }
}

// ------------------- pass 2 (mma): attO = E @ Vrt^T, K-chunk = 32 ----------------
static constexpr int A2_PITCH = 80;
static constexpr int A2_ATILE = 128 * A2_PITCH;            // 10240 per hi/lo
static constexpr int A2_BTILE = 64 * A2_PITCH;             // 5120
static constexpr int A2_STAGE = 2*A2_ATILE + 2*A2_BTILE;   // 30720
static constexpr int A2_SMEM  = 2 * A2_STAGE;              // 61440

__global__ __launch_bounds__(256, 2) void attn2_mma()
{
    extern __shared__ char smem[];
    const uint32_t sb = smem_u32(smem);
    int qt = blockIdx.x, bh = blockIdx.y;
    int b = bh >> 4, h = bh & 15;
    int q0 = qt * 128;
    int tid = threadIdx.x, lane = tid & 31, warp = tid >> 5;
    int wm = warp >> 1, wn = warp & 1;
    int nch = (qt + 1) * 4;

    float acc[2][4][4];
#pragma unroll
    for (int i = 0; i < 2; i++)
#pragma unroll
        for (int j = 0; j < 4; j++)
#pragma unroll
            for (int k = 0; k < 4; k++) acc[i][j][k] = 0.f;

    auto load_stage = [&](int st, int c) {
        int k0 = c * 32;
        uint32_t sbase = sb + st * A2_STAGE;
#pragma unroll
        for (int i = 0; i < 2; i++) {
            int idx = tid + i * 256;
            int row = idx >> 2, sg = idx & 3;
            size_t gi = ((size_t)bh*SS + q0 + row) * SS + k0 + sg * 8;
            cpa16(sbase + row * A2_PITCH + sg * 16, &g_Ehi[gi]);
            cpa16(sbase + A2_ATILE + row * A2_PITCH + sg * 16, &g_Elo[gi]);
        }
        {
            int row = tid >> 2, sg = tid & 3;
            size_t gi = ((size_t)bh*64 + row) * SS + k0 + sg * 8;
            cpa16(sbase + 2*A2_ATILE + row * A2_PITCH + sg * 16, &g_Vrth[gi]);
            cpa16(sbase + 2*A2_ATILE + A2_BTILE + row * A2_PITCH + sg * 16, &g_Vrtl[gi]);
        }
    };

    auto compute_stage = [&](int st) {
        uint32_t ab = sb + st * A2_STAGE;
#pragma unroll
        for (int kk = 0; kk < 2; kk++) {
            uint32_t ahr[2][4], alr[2][4], bhf[4][2], blf[4][2];
            uint32_t aoff = (uint32_t)(wm*32 + (lane & 15)) * A2_PITCH
                          + (uint32_t)(kk*16 + (lane >> 4) * 8) * 2;
#pragma unroll
            for (int mt = 0; mt < 2; mt++) {
                LDSM4(ahr[mt], ab + aoff + mt * (16*A2_PITCH));
                LDSM4(alr[mt], ab + A2_ATILE + aoff + mt * (16*A2_PITCH));
            }
            uint32_t boff = (uint32_t)(wn*32 + (lane & 7) + ((lane >> 4) << 3)) * A2_PITCH
                          + (uint32_t)(kk*16 + ((lane >> 3) & 1) * 8) * 2;
            {
                uint32_t t0[4], t1[4];
                LDSM4(t0, ab + 2*A2_ATILE + boff);
                LDSM4(t1, ab + 2*A2_ATILE + boff + 16*A2_PITCH);
                bhf[0][0]=t0[0]; bhf[0][1]=t0[1]; bhf[1][0]=t0[2]; bhf[1][1]=t0[3];
                bhf[2][0]=t1[0]; bhf[2][1]=t1[1]; bhf[3][0]=t1[2]; bhf[3][1]=t1[3];
                LDSM4(t0, ab + 2*A2_ATILE + A2_BTILE + boff);
                LDSM4(t1, ab + 2*A2_ATILE + A2_BTILE + boff + 16*A2_PITCH);
                blf[0][0]=t0[0]; blf[0][1]=t0[1]; blf[1][0]=t0[2]; blf[1][1]=t0[3];
                blf[2][0]=t1[0]; blf[2][1]=t1[1]; blf[3][0]=t1[2]; blf[3][1]=t1[3];
            }
#pragma unroll
            for (int mt = 0; mt < 2; mt++)
#pragma unroll
                for (int nt = 0; nt < 4; nt++) {
                    MMA16816(acc[mt][nt], ahr[mt], bhf[nt][0], bhf[nt][1]);
                    MMA16816(acc[mt][nt], ahr[mt], blf[nt][0], blf[nt][1]);
                    MMA16816(acc[mt][nt], alr[mt], bhf[nt][0], bhf[nt][1]);
                }
        }
    };

    load_stage(0, 0);
    CPA_COMMIT();
    load_stage(1, 1);
    CPA_COMMIT();

    for (int c = 0; c < nch; c++) {
        CPA_WAIT1();
        __syncthreads();
        compute_stage(c & 1);
        __syncthreads();
        if (c + 2 < nch) load_stage(c & 1, c + 2);
        CPA_COMMIT();
    }

    int r_ = lane >> 2, c_ = (lane & 3) * 2;
#pragma unroll
    for (int mt = 0; mt < 2; mt++)
#pragma unroll
        for (int nt = 0; nt < 4; nt++) {
            int q  = q0 + wm*32 + mt*16 + r_;
            int d  = wn*32 + nt*8 + c_;
            float v00 = acc[mt][nt][0], v01 = acc[mt][nt][1];
            float v10 = acc[mt][nt][2], v11 = acc[mt][nt][3];
            size_t i0 = (size_t)(b*SS + q) * HDIM + h*64 + d;
            size_t i1 = (size_t)(b*SS + q + 8) * HDIM + h*64 + d;
            __nv_bfloat16 h00 = __float2bfloat16(v00), h01 = __float2bfloat16(v01);
            __nv_bfloat16 h10 = __float2bfloat16(v10), h11 = __float2bfloat16(v11);
            __nv_bfloat162 hp0 = {h00, h01}, hp1 = {h10, h11};
            __nv_bfloat162 lp0 = {__float2bfloat16(v00 - __bfloat162float(h00)),
                                  __float2bfloat16(v01 - __bfloat162float(h01))};
            __nv_bfloat162 lp1 = {__float2bfloat16(v10 - __bfloat162float(h10)),
                                  __float2bfloat16(v11 - __bfloat162float(h11))};
            *(__nv_bfloat162*)&g_aoh[i0] = hp0;  *(__nv_bfloat162*)&g_aol[i0] = lp0;
            *(__nv_bfloat162*)&g_aoh[i1] = hp1;  *(__nv_bfloat162*)&g_aol[i1] = lp1;
        }
}

// ------------------- launch ------------------------------------------------------
extern "C" void kernel_launch(void* const* d_in, const int* in_sizes, int n_in,
                              void* d_out, int out_size)
{
    const float* queries = (const float*)d_in[0];
    const float* keys    = (const float*)d_in[1];
    const float* values  = (const float*)d_in[2];
    const float* Wq_w = (const float*)d_in[3];  const float* Wq_b = (const float*)d_in[4];
    const float* Wk_w = (const float*)d_in[5];  const float* Wk_b = (const float*)d_in[6];
    const float* Wv_w = (const float*)d_in[7];  const float* Wv_b = (const float*)d_in[8];
    const float* Aq_w = (const float*)d_in[9];  const float* Aq_b = (const float*)d_in[10];
    const float* Bq_w = (const float*)d_in[11]; const float* Bq_b = (const float*)d_in[12];
    const float* Ak_w = (const float*)d_in[13]; const float* Ak_b = (const float*)d_in[14];
    const float* Bk_w = (const float*)d_in[15]; const float* Bk_b = (const float*)d_in[16];
    const float* Av_w = (const float*)d_in[17]; const float* Av_b = (const float*)d_in[18];
    const float* Bv_w = (const float*)d_in[19]; const float* Bv_b = (const float*)d_in[20];
    const float* Wo_w = (const float*)d_in[21]; const float* Wo_b = (const float*)d_in[22];
    float* out = (float*)d_out;

    cudaFuncSetAttribute(gemm_mma, cudaFuncAttributeMaxDynamicSharedMemorySize, GEMM_SMEM);
    cudaFuncSetAttribute(attn1_mma, cudaFuncAttributeMaxDynamicSharedMemorySize, A1_SMEM);
    cudaFuncSetAttribute(attn2_mma, cudaFuncAttributeMaxDynamicSharedMemorySize, A2_SMEM);

    void *pbeq, *pbek, *pbev, *pV, *pcs, *pKA;
    void *pqh, *pql, *pkh, *pkl, *pvh, *pvl, *paoh, *paol;
    void *pQph, *pQpl, *pKph, *pKpl;
    void *pwqh, *pwql, *pwkh, *pwkl, *pwvh, *pwvl, *pwoh, *pwol;
    cudaGetSymbolAddress(&pbeq, g_beq); cudaGetSymbolAddress(&pbek, g_bek);
    cudaGetSymbolAddress(&pbev, g_bev); cudaGetSymbolAddress(&pV, g_V);
    cudaGetSymbolAddress(&pcs, g_colsum); cudaGetSymbolAddress(&pKA, g_KA);
    cudaGetSymbolAddress(&pqh, g_qh); cudaGetSymbolAddress(&pql, g_ql);
    cudaGetSymbolAddress(&pkh, g_kh); cudaGetSymbolAddress(&pkl, g_kl);
    cudaGetSymbolAddress(&pvh, g_vh); cudaGetSymbolAddress(&pvl, g_vl);
    cudaGetSymbolAddress(&paoh, g_aoh); cudaGetSymbolAddress(&paol, g_aol);
    cudaGetSymbolAddress(&pQph, g_Qph); cudaGetSymbolAddress(&pQpl, g_Qpl);
    cudaGetSymbolAddress(&pKph, g_Kph); cudaGetSymbolAddress(&pKpl, g_Kpl);
    cudaGetSymbolAddress(&pwqh, g_wqh); cudaGetSymbolAddress(&pwql, g_wql);
    cudaGetSymbolAddress(&pwkh, g_wkh); cudaGetSymbolAddress(&pwkl, g_wkl);
    cudaGetSymbolAddress(&pwvh, g_wvh); cudaGetSymbolAddress(&pwvl, g_wvl);
    cudaGetSymbolAddress(&pwoh, g_woh); cudaGetSymbolAddress(&pwol, g_wol);

    const int actblocks = (TOK * DMODEL / 4) / 256;
    const dim3 wgrid(DMODEL/32, HDIM/32);
    const dim3 ggrid(HDIM/128, TOK/128);

    // launches 0..4 (deps for gemm_Q) — launch #5 is gemm_Q for ncu -s 5
    actconv_kernel<<<actblocks, 256>>>(queries, (__nv_bfloat16*)pqh, (__nv_bfloat16*)pql);      // 0
    wprep_kernel<<<wgrid, 256>>>(Wq_w, Aq_w, Bq_w, (__nv_bfloat16*)pwqh, (__nv_bfloat16*)pwql); // 1
    beff_kernel<<<HDIM/256, 256>>>(Wq_b, Aq_b, Bq_w, Bq_b, (float*)pbeq);                       // 2
    actconv_kernel<<<actblocks, 256>>>(keys, (__nv_bfloat16*)pkh, (__nv_bfloat16*)pkl);         // 3
    wprep_kernel<<<wgrid, 256>>>(Wk_w, Ak_w, Bk_w, (__nv_bfloat16*)pwkh, (__nv_bfloat16*)pwkl); // 4

    gemm_mma<<<ggrid, 256, GEMM_SMEM>>>(                                                        // 5
        (const __nv_bfloat16*)pqh, (const __nv_bfloat16*)pql,
        (const __nv_bfloat16*)pwqh, (const __nv_bfloat16*)pwql,
        (const float*)pbeq, nullptr, nullptr,
        nullptr, (__nv_bfloat16*)pQph, (__nv_bfloat16*)pQpl);

    beff_kernel<<<HDIM/256, 256>>>(Wk_b, Ak_b, Bk_w, Bk_b, (float*)pbek);
    gemm_mma<<<ggrid, 256, GEMM_SMEM>>>(
        (const __nv_bfloat16*)pkh, (const __nv_bfloat16*)pkl,
        (const __nv_bfloat16*)pwkh, (const __nv_bfloat16*)pwkl,
        (const float*)pbek, nullptr, nullptr,
        nullptr, (__nv_bfloat16*)pKph, (__nv_bfloat16*)pKpl);

    actconv_kernel<<<actblocks, 256>>>(values, (__nv_bfloat16*)pvh, (__nv_bfloat16*)pvl);
    wprep_kernel<<<wgrid, 256>>>(Wv_w, nullptr, nullptr, (__nv_bfloat16*)pwvh, (__nv_bfloat16*)pwvl);
    beff_kernel<<<HDIM/256, 256>>>(Wv_b, Av_b, Bv_w, Bv_b, (float*)pbev);
    ka_kernel<<<TOK/8, 256>>>(keys, Av_w, (float*)pKA);

    // V = values@Wv + KA@Bv (rank-8 epilogue) + bev
    gemm_mma<<<ggrid, 256, GEMM_SMEM>>>(
        (const __nv_bfloat16*)pvh, (const __nv_bfloat16*)pvl,
        (const __nv_bfloat16*)pwvh, (const __nv_bfloat16*)pwvl,
        (const float*)pbev, (const float*)pKA, Bv_w,
        (float*)pV, nullptr, nullptr);

    zero_kernel<<<(BB*NH*SS)/256, 256>>>((float*)pcs);
    wprep_kernel<<<wgrid, 256>>>(Wo_w, nullptr, nullptr, (__nv_bfloat16*)pwoh, (__nv_bfloat16*)pwol);

    attn1_mma<<<dim3(16, 16, BB*NH), 256, A1_SMEM>>>();
    vrt_kernel<<<dim3(SS/32, 2, BB*NH), 256>>>();
    attn2_mma<<<dim3(16, BB*NH), 256, A2_SMEM>>>();

    gemm_mma<<<ggrid, 256, GEMM_SMEM>>>(
        (const __nv_bfloat16*)paoh, (const __nv_bfloat16*)paol,
        (const __nv_bfloat16*)pwoh, (const __nv_bfloat16*)pwol,
        Wo_b, nullptr, nullptr,
        out, nullptr, nullptr);
}

// round 6
// speedup vs baseline: 2.2845x; 1.0177x over previous
#include <cuda_runtime.h>
#include <cuda_bf16.h>
#include <math.h>
#include <stdint.h>

#define BB     4
#define SS     2048
#define DMODEL 1024
#define NH     16
#define HD     64
#define HDIM   1024
#define RK     8
#define TOK    (BB*SS)   // 8192

// ------------------- device scratch (static; allocation-free) -------------------
__device__ float g_beq[HDIM];
__device__ float g_bek[HDIM];
__device__ float g_bev[HDIM];
__device__ float g_V[(size_t)TOK*HDIM];
__device__ float g_colsum[(size_t)BB*NH*SS];
__device__ float g_KA[(size_t)TOK*RK];

__device__ __nv_bfloat16 g_qh[(size_t)TOK*DMODEL], g_ql[(size_t)TOK*DMODEL];
__device__ __nv_bfloat16 g_kh[(size_t)TOK*DMODEL], g_kl[(size_t)TOK*DMODEL];
__device__ __nv_bfloat16 g_vh[(size_t)TOK*DMODEL], g_vl[(size_t)TOK*DMODEL];
__device__ __nv_bfloat16 g_Qph[(size_t)TOK*HDIM], g_Qpl[(size_t)TOK*HDIM];
__device__ __nv_bfloat16 g_Kph[(size_t)TOK*HDIM], g_Kpl[(size_t)TOK*HDIM];
__device__ __nv_bfloat16 g_aoh[(size_t)TOK*HDIM], g_aol[(size_t)TOK*HDIM];
__device__ __nv_bfloat16 g_Ehi[(size_t)BB*NH*SS*SS];
__device__ __nv_bfloat16 g_Elo[(size_t)BB*NH*SS*SS];
__device__ __nv_bfloat16 g_Vrth[(size_t)BB*NH*64*SS];
__device__ __nv_bfloat16 g_Vrtl[(size_t)BB*NH*64*SS];
__device__ __nv_bfloat16 g_wqh[DMODEL*HDIM], g_wql[DMODEL*HDIM];
__device__ __nv_bfloat16 g_wkh[DMODEL*HDIM], g_wkl[DMODEL*HDIM];
__device__ __nv_bfloat16 g_wvh[DMODEL*HDIM], g_wvl[DMODEL*HDIM];
__device__ __nv_bfloat16 g_woh[DMODEL*HDIM], g_wol[DMODEL*HDIM];

// ------------------- helpers ------------------------------------------------------
__device__ __forceinline__ uint32_t smem_u32(const void* p) {
    uint32_t a;
    asm("{ .reg .u64 t; cvta.to.shared.u64 t, %1; cvt.u32.u64 %0, t; }" : "=r"(a) : "l"(p));
    return a;
}
__device__ __forceinline__ void cpa16(uint32_t dst, const void* src) {
    asm volatile("cp.async.cg.shared.global [%0], [%1], 16;"
                 :: "r"(dst), "l"(__cvta_generic_to_global(src)));
}
#define CPA_COMMIT() asm volatile("cp.async.commit_group;")
#define CPA_WAIT1()  asm volatile("cp.async.wait_group 1;")
#define CPA_WAIT2()  asm volatile("cp.async.wait_group 2;")
#define CPA_WAIT0()  asm volatile("cp.async.wait_group 0;")

#define LDSM4(r, a) \
    asm volatile("ldmatrix.sync.aligned.m8n8.x4.shared.b16 {%0,%1,%2,%3}, [%4];" \
        : "=r"((r)[0]), "=r"((r)[1]), "=r"((r)[2]), "=r"((r)[3]) : "r"(a))

#define MMA16816(c, a, b0, b1) \
    asm volatile("mma.sync.aligned.m16n8k16.row.col.f32.bf16.bf16.f32 " \
        "{%0,%1,%2,%3}, {%4,%5,%6,%7}, {%8,%9}, {%0,%1,%2,%3};" \
        : "+f"((c)[0]), "+f"((c)[1]), "+f"((c)[2]), "+f"((c)[3]) \
        : "r"((a)[0]), "r"((a)[1]), "r"((a)[2]), "r"((a)[3]), "r"(b0), "r"(b1))

// ------------------- fused prep kernels -------------------------------------------
struct ActArgs { const float* X[3]; __nv_bfloat16 *hi[3], *lo[3]; };
__global__ void actconv_kernel(ActArgs aa)
{
    int z = blockIdx.z;
    const float* X = aa.X[z];
    __nv_bfloat16* hi = aa.hi[z];
    __nv_bfloat16* lo = aa.lo[z];
    size_t i = ((size_t)blockIdx.x * 256 + threadIdx.x) * 4;
    float4 v = *(const float4*)&X[i];
    __nv_bfloat16 h0 = __float2bfloat16(v.x), h1 = __float2bfloat16(v.y);
    __nv_bfloat16 h2 = __float2bfloat16(v.z), h3 = __float2bfloat16(v.w);
    __nv_bfloat162 ph0 = {h0, h1}, ph1 = {h2, h3};
    __nv_bfloat162 pl0 = {__float2bfloat16(v.x - __bfloat162float(h0)),
                          __float2bfloat16(v.y - __bfloat162float(h1))};
    __nv_bfloat162 pl1 = {__float2bfloat16(v.z - __bfloat162float(h2)),
                          __float2bfloat16(v.w - __bfloat162float(h3))};
    *(__nv_bfloat162*)&hi[i]   = ph0;  *(__nv_bfloat162*)&hi[i+2] = ph1;
    *(__nv_bfloat162*)&lo[i]   = pl0;  *(__nv_bfloat162*)&lo[i+2] = pl1;
}

struct WprepArgs { const float *W[4], *A[4], *Bw[4]; __nv_bfloat16 *hi[4], *lo[4]; };
__global__ __launch_bounds__(256) void wprep_kernel(WprepArgs wa)
{
    __shared__ float t[32][33];
    int z = blockIdx.z;
    const float* W = wa.W[z];
    const float* A = wa.A[z];
    const float* Bw = wa.Bw[z];
    __nv_bfloat16* hi = wa.hi[z];
    __nv_bfloat16* lo = wa.lo[z];
    int kb = blockIdx.x * 32, nb = blockIdx.y * 32;
    int x = threadIdx.x & 31, y = threadIdx.x >> 5;
#pragma unroll
    for (int i = y; i < 32; i += 8) {
        int k = kb + i, n = nb + x;
        float v = W[(size_t)k*HDIM + n];
        if (A) {
#pragma unroll
            for (int r = 0; r < RK; r++) v += A[k*RK + r] * Bw[r*HDIM + n];
        }
        t[i][x] = v;
    }
    __syncthreads();
#pragma unroll
    for (int i = y; i < 32; i += 8) {
        int n = nb + i, k = kb + x;
        float v = t[x][i];
        __nv_bfloat16 h = __float2bfloat16(v);
        hi[(size_t)n*DMODEL + k] = h;
        lo[(size_t)n*DMODEL + k] = __float2bfloat16(v - __bfloat162float(h));
    }
}

struct BeffArgs { const float *Wb[3], *Ab[3], *Bw[3], *Bb[3]; float* out[3]; };
__global__ void beff_kernel(BeffArgs ba)
{
    int z = blockIdx.z;
    int j = blockIdx.x * 256 + threadIdx.x;
    float acc = ba.Wb[z][j] + ba.Bb[z][j];
    const float* Ab = ba.Ab[z];
    const float* Bw = ba.Bw[z];
#pragma unroll
    for (int r = 0; r < RK; r++) acc += Ab[r] * Bw[r*HDIM + j];
    ba.out[z][j] = acc;
}

__global__ void zero_kernel(float* p) { p[blockIdx.x * 256 + threadIdx.x] = 0.f; }

__global__ __launch_bounds__(256) void ka_kernel(const float* __restrict__ keys,
                                                 const float* __restrict__ Av,
                                                 float* __restrict__ KA)
{
    int row = blockIdx.x * 8 + (threadIdx.x >> 5);
    int lane = threadIdx.x & 31;
    float acc[RK];
#pragma unroll
    for (int r = 0; r < RK; r++) acc[r] = 0.f;
    const float* kr = keys + (size_t)row * DMODEL;
    for (int k = lane; k < DMODEL; k += 32) {
        float kv = kr[k];
#pragma unroll
        for (int r = 0; r < RK; r++) acc[r] += kv * Av[k*RK + r];
    }
#pragma unroll
    for (int r = 0; r < RK; r++) {
#pragma unroll
        for (int off = 16; off > 0; off >>= 1)
            acc[r] += __shfl_down_sync(0xffffffffu, acc[r], off);
    }
    if (lane == 0) {
#pragma unroll
        for (int r = 0; r < RK; r++) KA[(size_t)row*RK + r] = acc[r];
    }
}

// ------------------- fused mma.sync split-bf16 GEMM -------------------------------
static constexpr int STAGE_BYTES = 40960;
static constexpr int GEMM_SMEM   = 2 * STAGE_BYTES;

struct GemmArgs {
    const __nv_bfloat16 *Ah[4], *Al[4], *Bh[4], *Bl[4];
    const float* bias[4];
    float* outF[4];
    __nv_bfloat16 *outH[4], *outL[4];
    const float *loraKA, *loraB;
};

__global__ __launch_bounds__(256, 2)
void gemm_mma(GemmArgs ga, int op)
{
    extern __shared__ char smem[];
    const uint32_t sb = smem_u32(smem);
    const int z = op ? 3 : blockIdx.z;
    const __nv_bfloat16* Ah = ga.Ah[z];
    const __nv_bfloat16* Al = ga.Al[z];
    const __nv_bfloat16* Bh = ga.Bh[z];
    const __nv_bfloat16* Bl = ga.Bl[z];
    const float* bias = ga.bias[z];
    float* outF = ga.outF[z];
    __nv_bfloat16* outH = ga.outH[z];
    __nv_bfloat16* outL = ga.outL[z];
    const float* loraKA = (z == 2) ? ga.loraKA : nullptr;
    const float* loraB  = ga.loraB;

    const int tid  = threadIdx.x;
    const int lane = tid & 31;
    const int warp = tid >> 5;
    const int wm = warp >> 2, wn = warp & 3;
    const int m0 = blockIdx.y * 128, n0 = blockIdx.x * 128;

    float acc[4][4][4];
#pragma unroll
    for (int i = 0; i < 4; i++)
#pragma unroll
        for (int j = 0; j < 4; j++)
#pragma unroll
            for (int k = 0; k < 4; k++) acc[i][j][k] = 0.f;

    auto load_stage = [&](int st, int chunk) {
        int k0 = chunk * 32;
        const __nv_bfloat16* tp[4] = {Ah, Al, Bh, Bl};
        uint32_t sbase = sb + st * STAGE_BYTES;
#pragma unroll
        for (int i = 0; i < 8; i++) {
            const int t = i >> 1;
            int j = (i & 1) ? tid + 256 : tid;
            int row = j >> 2, sg = j & 3;
            int r0 = (t < 2) ? m0 : n0;
            cpa16(sbase + t * 10240 + row * 80 + sg * 16,
                  tp[t] + (size_t)(r0 + row) * 1024 + k0 + sg * 8);
        }
    };

    auto compute_stage = [&](int st) {
        uint32_t ab = sb + st * STAGE_BYTES;
#pragma unroll
        for (int kk = 0; kk < 2; kk++) {
            uint32_t ahr[4][4], alr[4][4], bh2[4][2], bl2[4][2];
            uint32_t aoff = (uint32_t)(wm*64 + (lane & 15)) * 80
                          + (uint32_t)(kk*16 + (lane >> 4) * 8) * 2;
#pragma unroll
            for (int mt = 0; mt < 4; mt++) {
                LDSM4(ahr[mt], ab + aoff + mt * (16*80));
                LDSM4(alr[mt], ab + 10240 + aoff + mt * (16*80));
            }
            uint32_t boff = (uint32_t)(wn*32 + (lane & 7) + ((lane >> 4) << 3)) * 80
                          + (uint32_t)(kk*16 + ((lane >> 3) & 1) * 8) * 2;
            {
                uint32_t t0[4], t1[4];
                LDSM4(t0, ab + 20480 + boff);
                LDSM4(t1, ab + 20480 + boff + 16*80);
                bh2[0][0]=t0[0]; bh2[0][1]=t0[1]; bh2[1][0]=t0[2]; bh2[1][1]=t0[3];
                bh2[2][0]=t1[0]; bh2[2][1]=t1[1]; bh2[3][0]=t1[2]; bh2[3][1]=t1[3];
                LDSM4(t0, ab + 30720 + boff);
                LDSM4(t1, ab + 30720 + boff + 16*80);
                bl2[0][0]=t0[0]; bl2[0][1]=t0[1]; bl2[1][0]=t0[2]; bl2[1][1]=t0[3];
                bl2[2][0]=t1[0]; bl2[2][1]=t1[1]; bl2[3][0]=t1[2]; bl2[3][1]=t1[3];
            }
#pragma unroll
            for (int mt = 0; mt < 4; mt++)
#pragma unroll
                for (int nt = 0; nt < 4; nt++) {
                    MMA16816(acc[mt][nt], ahr[mt], bh2[nt][0], bh2[nt][1]);
                    MMA16816(acc[mt][nt], ahr[mt], bl2[nt][0], bl2[nt][1]);
                    MMA16816(acc[mt][nt], alr[mt], bh2[nt][0], bh2[nt][1]);
                }
        }
    };

    load_stage(0, 0);
    CPA_COMMIT();
    load_stage(1, 1);
    CPA_COMMIT();

#pragma unroll 1
    for (int c = 0; c < 32; c++) {
        CPA_WAIT1();
        __syncthreads();
        compute_stage(c & 1);
        __syncthreads();
        if (c + 2 < 32) load_stage(c & 1, c + 2);
        CPA_COMMIT();
    }

    int r_ = lane >> 2, c_ = (lane & 3) * 2;
#pragma unroll
    for (int mt = 0; mt < 4; mt++) {
        int row = m0 + wm*64 + mt*16 + r_;
        float ka0[RK], ka1[RK];
        if (loraKA) {
#pragma unroll
            for (int r = 0; r < RK; r++) {
                ka0[r] = loraKA[(size_t)row*RK + r];
                ka1[r] = loraKA[(size_t)(row+8)*RK + r];
            }
        }
#pragma unroll
        for (int nt = 0; nt < 4; nt++) {
            int col = n0 + wn*32 + nt*8 + c_;
            float b0 = bias[col], b1 = bias[col + 1];
            float v00 = acc[mt][nt][0] + b0, v01 = acc[mt][nt][1] + b1;
            float v10 = acc[mt][nt][2] + b0, v11 = acc[mt][nt][3] + b1;
            if (loraKA) {
#pragma unroll
                for (int r = 0; r < RK; r++) {
                    float w0 = loraB[r*HDIM + col], w1 = loraB[r*HDIM + col + 1];
                    v00 += ka0[r] * w0;  v01 += ka0[r] * w1;
                    v10 += ka1[r] * w0;  v11 += ka1[r] * w1;
                }
            }
            if (outF) {
                *(float2*)&outF[(size_t)row * 1024 + col] = {v00, v01};
                *(float2*)&outF[(size_t)(row + 8) * 1024 + col] = {v10, v11};
            } else {
                __nv_bfloat16 h00 = __float2bfloat16(v00), h01 = __float2bfloat16(v01);
                __nv_bfloat16 h10 = __float2bfloat16(v10), h11 = __float2bfloat16(v11);
                __nv_bfloat162 hp0 = {h00, h01}, hp1 = {h10, h11};
                __nv_bfloat162 lp0 = {__float2bfloat16(v00 - __bfloat162float(h00)),
                                      __float2bfloat16(v01 - __bfloat162float(h01))};
                __nv_bfloat162 lp1 = {__float2bfloat16(v10 - __bfloat162float(h10)),
                                      __float2bfloat16(v11 - __bfloat162float(h11))};
                *(__nv_bfloat162*)&outH[(size_t)row * 1024 + col] = hp0;
                *(__nv_bfloat162*)&outH[(size_t)(row + 8) * 1024 + col] = hp1;
                *(__nv_bfloat162*)&outL[(size_t)row * 1024 + col] = lp0;
                *(__nv_bfloat162*)&outL[(size_t)(row + 8) * 1024 + col] = lp1;
            }
        }
    }
}

// ------------------- pass 1 (mma): E = exp(QK^T) masked, column sums -------------
static constexpr int A1_PITCH = 144;
static constexpr int A1_TILE  = 128 * A1_PITCH;
static constexpr int A1_SMEM  = 4 * A1_TILE;

__global__ __launch_bounds__(256, 2) void attn1_mma()
{
    extern __shared__ char smem[];
    // triangular decode: blockIdx.x in [0,136) -> (qt,kt) with kt<=qt
    int idx = blockIdx.x;
    int qt = (int)((sqrtf(8.f*idx + 1.f) - 1.f) * 0.5f);
    if ((qt+1)*(qt+2)/2 <= idx) qt++;
    if (qt*(qt+1)/2 > idx) qt--;
    int kt = idx - qt*(qt+1)/2;
    int bh = blockIdx.y;
    const uint32_t sb = smem_u32(smem);
    int b = bh >> 4, h = bh & 15;
    int q0 = qt * 128, k0 = kt * 128;
    int tid = threadIdx.x, lane = tid & 31, warp = tid >> 5;
    int wm = warp >> 2, wn = warp & 3;

    {
        const __nv_bfloat16* tp[4] = {g_Qph, g_Qpl, g_Kph, g_Kpl};
#pragma unroll
        for (int t = 0; t < 4; t++) {
            int r0 = (t < 2) ? q0 : k0;
#pragma unroll
            for (int i = 0; i < 4; i++) {
                int ix = tid + i * 256;
                int row = ix >> 3, sg = ix & 7;
                cpa16(sb + t * A1_TILE + row * A1_PITCH + sg * 16,
                      tp[t] + (size_t)(b*SS + r0 + row) * 1024 + h*64 + sg * 8);
            }
        }
    }
    CPA_COMMIT(); CPA_WAIT0();
    __syncthreads();

    float acc[4][4][4];
#pragma unroll
    for (int i = 0; i < 4; i++)
#pragma unroll
        for (int j = 0; j < 4; j++)
#pragma unroll
            for (int k = 0; k < 4; k++) acc[i][j][k] = 0.f;

#pragma unroll
    for (int kk = 0; kk < 4; kk++) {
        uint32_t ahr[4][4], alr[4][4], bhf[4][2], blf[4][2];
        uint32_t aoff = (uint32_t)(wm*64 + (lane & 15)) * A1_PITCH
                      + (uint32_t)(kk*16 + (lane >> 4) * 8) * 2;
#pragma unroll
        for (int mt = 0; mt < 4; mt++) {
            LDSM4(ahr[mt], sb + aoff + mt * (16*A1_PITCH));
            LDSM4(alr[mt], sb + A1_TILE + aoff + mt * (16*A1_PITCH));
        }
        uint32_t boff = (uint32_t)(wn*32 + (lane & 7) + ((lane >> 4) << 3)) * A1_PITCH
                      + (uint32_t)(kk*16 + ((lane >> 3) & 1) * 8) * 2;
        {
            uint32_t t0[4], t1[4];
            LDSM4(t0, sb + 2*A1_TILE + boff);
            LDSM4(t1, sb + 2*A1_TILE + boff + 16*A1_PITCH);
            bhf[0][0]=t0[0]; bhf[0][1]=t0[1]; bhf[1][0]=t0[2]; bhf[1][1]=t0[3];
            bhf[2][0]=t1[0]; bhf[2][1]=t1[1]; bhf[3][0]=t1[2]; bhf[3][1]=t1[3];
            LDSM4(t0, sb + 3*A1_TILE + boff);
            LDSM4(t1, sb + 3*A1_TILE + boff + 16*A1_PITCH);
            blf[0][0]=t0[0]; blf[0][1]=t0[1]; blf[1][0]=t0[2]; blf[1][1]=t0[3];
            blf[2][0]=t1[0]; blf[2][1]=t1[1]; blf[3][0]=t1[2]; blf[3][1]=t1[3];
        }
#pragma unroll
        for (int mt = 0; mt < 4; mt++)
#pragma unroll
            for (int nt = 0; nt < 4; nt++) {
                MMA16816(acc[mt][nt], ahr[mt], bhf[nt][0], bhf[nt][1]);
                MMA16816(acc[mt][nt], ahr[mt], blf[nt][0], blf[nt][1]);
                MMA16816(acc[mt][nt], alr[mt], bhf[nt][0], bhf[nt][1]);
            }
    }

    __syncthreads();
    float* cs = (float*)smem;
    if (tid < 128) cs[tid] = 0.f;
    __syncthreads();

    const bool diag = (qt == kt);
    int r_ = lane >> 2, c_ = (lane & 3) * 2;
    float cs0[4] = {0,0,0,0}, cs1[4] = {0,0,0,0};
#pragma unroll
    for (int mt = 0; mt < 4; mt++) {
        int qb = q0 + wm*64 + mt*16;
#pragma unroll
        for (int nt = 0; nt < 4; nt++) {
            int k = k0 + wn*32 + nt*8 + c_;
            float e00 = __expf(acc[mt][nt][0]);
            float e01 = __expf(acc[mt][nt][1]);
            float e10 = __expf(acc[mt][nt][2]);
            float e11 = __expf(acc[mt][nt][3]);
            int qr0 = qb + r_, qr1 = qb + r_ + 8;
            if (diag) {
                if (qr0 < k)     e00 = 0.f;
                if (qr0 < k + 1) e01 = 0.f;
                if (qr1 < k)     e10 = 0.f;
                if (qr1 < k + 1) e11 = 0.f;
            }
            cs0[nt] += e00 + e10;
            cs1[nt] += e01 + e11;
            __nv_bfloat16 h00 = __float2bfloat16(e00), h01 = __float2bfloat16(e01);
            __nv_bfloat16 h10 = __float2bfloat16(e10), h11 = __float2bfloat16(e11);
            __nv_bfloat162 hp0 = {h00, h01}, hp1 = {h10, h11};
            __nv_bfloat162 lp0 = {__float2bfloat16(e00 - __bfloat162float(h00)),
                                  __float2bfloat16(e01 - __bfloat162float(h01))};
            __nv_bfloat162 lp1 = {__float2bfloat16(e10 - __bfloat162float(h10)),
                                  __float2bfloat16(e11 - __bfloat162float(h11))};
            size_t b0i = ((size_t)bh*SS + qr0) * SS + k;
            size_t b1i = ((size_t)bh*SS + qr1) * SS + k;
            *(__nv_bfloat162*)&g_Ehi[b0i] = hp0;  *(__nv_bfloat162*)&g_Elo[b0i] = lp0;
            *(__nv_bfloat162*)&g_Ehi[b1i] = hp1;  *(__nv_bfloat162*)&g_Elo[b1i] = lp1;
        }
    }
#pragma unroll
    for (int nt = 0; nt < 4; nt++) {
        atomicAdd(&cs[wn*32 + nt*8 + c_],     cs0[nt]);
        atomicAdd(&cs[wn*32 + nt*8 + c_ + 1], cs1[nt]);
    }
    __syncthreads();
    if (tid < 128)
        atomicAdd(&g_colsum[(size_t)bh*SS + k0 + tid], cs[tid]);
}

// ------------------- Vrt prep ------------------------------------------------------
__global__ __launch_bounds__(256) void vrt_kernel()
{
    __shared__ float t[32][33];
    int kt = blockIdx.x, dt = blockIdx.y, bh = blockIdx.z;
    int b = bh >> 4, h = bh & 15;
    int k0 = kt * 32, d0 = dt * 32;
    int x = threadIdx.x & 31, y = threadIdx.x >> 5;
#pragma unroll
    for (int i = y; i < 32; i += 8) {
        int k = k0 + i;
        float r = 1.0f / (g_colsum[(size_t)bh*SS + k] * 8.0f);
        t[i][x] = g_V[(size_t)(b*SS + k) * HDIM + h*64 + d0 + x] * r;
    }
    __syncthreads();
#pragma unroll
    for (int i = y; i < 32; i += 8) {
        int d = d0 + i, k = k0 + x;
        float v = t[x][i];
        __nv_bfloat16 hh = __float2bfloat16(v);
        size_t idx = ((size_t)bh*64 + d) * SS + k;
        g_Vrth[idx] = hh;
        g_Vrtl[idx] = __float2bfloat16(v - __bfloat162float(hh));
    }
}

// ------------------- pass 2 (mma): attO = E @ Vrt^T, 3-stage, LPT ----------------
static constexpr int A2_PITCH = 80;
static constexpr int A2_ATILE = 128 * A2_PITCH;
static constexpr int A2_BTILE = 64 * A2_PITCH;
static constexpr int A2_STAGE = 2*A2_ATILE + 2*A2_BTILE;   // 30720
static constexpr int A2_SMEM  = 3 * A2_STAGE;              // 92160

__global__ __launch_bounds__(256, 2) void attn2_mma()
{
    extern __shared__ char smem[];
    const uint32_t sb = smem_u32(smem);
    int qt = (int)gridDim.x - 1 - (int)blockIdx.x;    // LPT: heavy tiles first
    int bh = blockIdx.y;
    int b = bh >> 4, h = bh & 15;
    int q0 = qt * 128;
    int tid = threadIdx.x, lane = tid & 31, warp = tid >> 5;
    int wm = warp >> 1, wn = warp & 1;
    int nch = (qt + 1) * 4;

    float acc[2][4][4];
#pragma unroll
    for (int i = 0; i < 2; i++)
#pragma unroll
        for (int j = 0; j < 4; j++)
#pragma unroll
            for (int k = 0; k < 4; k++) acc[i][j][k] = 0.f;

    auto load_stage = [&](int st, int c) {
        int k0 = c * 32;
        uint32_t sbase = sb + st * A2_STAGE;
#pragma unroll
        for (int i = 0; i < 2; i++) {
            int ix = tid + i * 256;
            int row = ix >> 2, sg = ix & 3;
            size_t gi = ((size_t)bh*SS + q0 + row) * SS + k0 + sg * 8;
            cpa16(sbase + row * A2_PITCH + sg * 16, &g_Ehi[gi]);
            cpa16(sbase + A2_ATILE + row * A2_PITCH + sg * 16, &g_Elo[gi]);
        }
        {
            int row = tid >> 2, sg = tid & 3;
            size_t gi = ((size_t)bh*64 + row) * SS + k0 + sg * 8;
            cpa16(sbase + 2*A2_ATILE + row * A2_PITCH + sg * 16, &g_Vrth[gi]);
            cpa16(sbase + 2*A2_ATILE + A2_BTILE + row * A2_PITCH + sg * 16, &g_Vrtl[gi]);
        }
    };

    auto compute_stage = [&](int st) {
        uint32_t ab = sb + st * A2_STAGE;
#pragma unroll
        for (int kk = 0; kk < 2; kk++) {
            uint32_t ahr[2][4], alr[2][4], bhf[4][2], blf[4][2];
            uint32_t aoff = (uint32_t)(wm*32 + (lane & 15)) * A2_PITCH
                          + (uint32_t)(kk*16 + (lane >> 4) * 8) * 2;
#pragma unroll
            for (int mt = 0; mt < 2; mt++) {
                LDSM4(ahr[mt], ab + aoff + mt * (16*A2_PITCH));
                LDSM4(alr[mt], ab + A2_ATILE + aoff + mt * (16*A2_PITCH));
            }
            uint32_t boff = (uint32_t)(wn*32 + (lane & 7) + ((lane >> 4) << 3)) * A2_PITCH
                          + (uint32_t)(kk*16 + ((lane >> 3) & 1) * 8) * 2;
            {
                uint32_t t0[4], t1[4];
                LDSM4(t0, ab + 2*A2_ATILE + boff);
                LDSM4(t1, ab + 2*A2_ATILE + boff + 16*A2_PITCH);
                bhf[0][0]=t0[0]; bhf[0][1]=t0[1]; bhf[1][0]=t0[2]; bhf[1][1]=t0[3];
                bhf[2][0]=t1[0]; bhf[2][1]=t1[1]; bhf[3][0]=t1[2]; bhf[3][1]=t1[3];
                LDSM4(t0, ab + 2*A2_ATILE + A2_BTILE + boff);
                LDSM4(t1, ab + 2*A2_ATILE + A2_BTILE + boff + 16*A2_PITCH);
                blf[0][0]=t0[0]; blf[0][1]=t0[1]; blf[1][0]=t0[2]; blf[1][1]=t0[3];
                blf[2][0]=t1[0]; blf[2][1]=t1[1]; blf[3][0]=t1[2]; blf[3][1]=t1[3];
            }
#pragma unroll
            for (int mt = 0; mt < 2; mt++)
#pragma unroll
                for (int nt = 0; nt < 4; nt++) {
                    MMA16816(acc[mt][nt], ahr[mt], bhf[nt][0], bhf[nt][1]);
                    MMA16816(acc[mt][nt], ahr[mt], blf[nt][0], blf[nt][1]);
                    MMA16816(acc[mt][nt], alr[mt], bhf[nt][0], bhf[nt][1]);
                }
        }
    };

    load_stage(0, 0);
    CPA_COMMIT();
    load_stage(1, 1);
    CPA_COMMIT();
    load_stage(2, 2);
    CPA_COMMIT();

    int st = 0;
    for (int c = 0; c < nch; c++) {
        CPA_WAIT2();
        __syncthreads();
        compute_stage(st);
        __syncthreads();
        if (c + 3 < nch) load_stage(st, c + 3);
        CPA_COMMIT();
        st = (st == 2) ? 0 : st + 1;
    }

    int r_ = lane >> 2, c_ = (lane & 3) * 2;
#pragma unroll
    for (int mt = 0; mt < 2; mt++)
#pragma unroll
        for (int nt = 0; nt < 4; nt++) {
            int q  = q0 + wm*32 + mt*16 + r_;
            int d  = wn*32 + nt*8 + c_;
            float v00 = acc[mt][nt][0], v01 = acc[mt][nt][1];
            float v10 = acc[mt][nt][2], v11 = acc[mt][nt][3];
            size_t i0 = (size_t)(b*SS + q) * HDIM + h*64 + d;
            size_t i1 = (size_t)(b*SS + q + 8) * HDIM + h*64 + d;
            __nv_bfloat16 h00 = __float2bfloat16(v00), h01 = __float2bfloat16(v01);
            __nv_bfloat16 h10 = __float2bfloat16(v10), h11 = __float2bfloat16(v11);
            __nv_bfloat162 hp0 = {h00, h01}, hp1 = {h10, h11};
            __nv_bfloat162 lp0 = {__float2bfloat16(v00 - __bfloat162float(h00)),
                                  __float2bfloat16(v01 - __bfloat162float(h01))};
            __nv_bfloat162 lp1 = {__float2bfloat16(v10 - __bfloat162float(h10)),
                                  __float2bfloat16(v11 - __bfloat162float(h11))};
            *(__nv_bfloat162*)&g_aoh[i0] = hp0;  *(__nv_bfloat162*)&g_aol[i0] = lp0;
            *(__nv_bfloat162*)&g_aoh[i1] = hp1;  *(__nv_bfloat162*)&g_aol[i1] = lp1;
        }
}

// ------------------- launch ------------------------------------------------------
extern "C" void kernel_launch(void* const* d_in, const int* in_sizes, int n_in,
                              void* d_out, int out_size)
{
    const float* queries = (const float*)d_in[0];
    const float* keys    = (const float*)d_in[1];
    const float* values  = (const float*)d_in[2];
    const float* Wq_w = (const float*)d_in[3];  const float* Wq_b = (const float*)d_in[4];
    const float* Wk_w = (const float*)d_in[5];  const float* Wk_b = (const float*)d_in[6];
    const float* Wv_w = (const float*)d_in[7];  const float* Wv_b = (const float*)d_in[8];
    const float* Aq_w = (const float*)d_in[9];  const float* Aq_b = (const float*)d_in[10];
    const float* Bq_w = (const float*)d_in[11]; const float* Bq_b = (const float*)d_in[12];
    const float* Ak_w = (const float*)d_in[13]; const float* Ak_b = (const float*)d_in[14];
    const float* Bk_w = (const float*)d_in[15]; const float* Bk_b = (const float*)d_in[16];
    const float* Av_w = (const float*)d_in[17]; const float* Av_b = (const float*)d_in[18];
    const float* Bv_w = (const float*)d_in[19]; const float* Bv_b = (const float*)d_in[20];
    const float* Wo_w = (const float*)d_in[21]; const float* Wo_b = (const float*)d_in[22];
    float* out = (float*)d_out;

    cudaFuncSetAttribute(gemm_mma, cudaFuncAttributeMaxDynamicSharedMemorySize, GEMM_SMEM);
    cudaFuncSetAttribute(attn1_mma, cudaFuncAttributeMaxDynamicSharedMemorySize, A1_SMEM);
    cudaFuncSetAttribute(attn2_mma, cudaFuncAttributeMaxDynamicSharedMemorySize, A2_SMEM);

    void *pbeq, *pbek, *pbev, *pV, *pcs, *pKA;
    void *pqh, *pql, *pkh, *pkl, *pvh, *pvl, *paoh, *paol;
    void *pQph, *pQpl, *pKph, *pKpl;
    void *pwqh, *pwql, *pwkh, *pwkl, *pwvh, *pwvl, *pwoh, *pwol;
    cudaGetSymbolAddress(&pbeq, g_beq); cudaGetSymbolAddress(&pbek, g_bek);
    cudaGetSymbolAddress(&pbev, g_bev); cudaGetSymbolAddress(&pV, g_V);
    cudaGetSymbolAddress(&pcs, g_colsum); cudaGetSymbolAddress(&pKA, g_KA);
    cudaGetSymbolAddress(&pqh, g_qh); cudaGetSymbolAddress(&pql, g_ql);
    cudaGetSymbolAddress(&pkh, g_kh); cudaGetSymbolAddress(&pkl, g_kl);
    cudaGetSymbolAddress(&pvh, g_vh); cudaGetSymbolAddress(&pvl, g_vl);
    cudaGetSymbolAddress(&paoh, g_aoh); cudaGetSymbolAddress(&paol, g_aol);
    cudaGetSymbolAddress(&pQph, g_Qph); cudaGetSymbolAddress(&pQpl, g_Qpl);
    cudaGetSymbolAddress(&pKph, g_Kph); cudaGetSymbolAddress(&pKpl, g_Kpl);
    cudaGetSymbolAddress(&pwqh, g_wqh); cudaGetSymbolAddress(&pwql, g_wql);
    cudaGetSymbolAddress(&pwkh, g_wkh); cudaGetSymbolAddress(&pwkl, g_wkl);
    cudaGetSymbolAddress(&pwvh, g_wvh); cudaGetSymbolAddress(&pwvl, g_wvl);
    cudaGetSymbolAddress(&pwoh, g_woh); cudaGetSymbolAddress(&pwol, g_wol);

    // ---- arg structs ----
    ActArgs aa;
    aa.X[0] = queries; aa.X[1] = keys; aa.X[2] = values;
    aa.hi[0] = (__nv_bfloat16*)pqh; aa.hi[1] = (__nv_bfloat16*)pkh; aa.hi[2] = (__nv_bfloat16*)pvh;
    aa.lo[0] = (__nv_bfloat16*)pql; aa.lo[1] = (__nv_bfloat16*)pkl; aa.lo[2] = (__nv_bfloat16*)pvl;

    WprepArgs wa;
    wa.W[0] = Wq_w; wa.W[1] = Wk_w; wa.W[2] = Wv_w; wa.W[3] = Wo_w;
    wa.A[0] = Aq_w; wa.A[1] = Ak_w; wa.A[2] = nullptr; wa.A[3] = nullptr;
    wa.Bw[0] = Bq_w; wa.Bw[1] = Bk_w; wa.Bw[2] = nullptr; wa.Bw[3] = nullptr;
    wa.hi[0] = (__nv_bfloat16*)pwqh; wa.hi[1] = (__nv_bfloat16*)pwkh;
    wa.hi[2] = (__nv_bfloat16*)pwvh; wa.hi[3] = (__nv_bfloat16*)pwoh;
    wa.lo[0] = (__nv_bfloat16*)pwql; wa.lo[1] = (__nv_bfloat16*)pwkl;
    wa.lo[2] = (__nv_bfloat16*)pwvl; wa.lo[3] = (__nv_bfloat16*)pwol;

    BeffArgs ba;
    ba.Wb[0] = Wq_b; ba.Wb[1] = Wk_b; ba.Wb[2] = Wv_b;
    ba.Ab[0] = Aq_b; ba.Ab[1] = Ak_b; ba.Ab[2] = Av_b;
    ba.Bw[0] = Bq_w; ba.Bw[1] = Bk_w; ba.Bw[2] = Bv_w;
    ba.Bb[0] = Bq_b; ba.Bb[1] = Bk_b; ba.Bb[2] = Bv_b;
    ba.out[0] = (float*)pbeq; ba.out[1] = (float*)pbek; ba.out[2] = (float*)pbev;

    GemmArgs ga;
    ga.Ah[0] = (const __nv_bfloat16*)pqh;  ga.Al[0] = (const __nv_bfloat16*)pql;
    ga.Ah[1] = (const __nv_bfloat16*)pkh;  ga.Al[1] = (const __nv_bfloat16*)pkl;
    ga.Ah[2] = (const __nv_bfloat16*)pvh;  ga.Al[2] = (const __nv_bfloat16*)pvl;
    ga.Ah[3] = (const __nv_bfloat16*)paoh; ga.Al[3] = (const __nv_bfloat16*)paol;
    ga.Bh[0] = (const __nv_bfloat16*)pwqh; ga.Bl[0] = (const __nv_bfloat16*)pwql;
    ga.Bh[1] = (const __nv_bfloat16*)pwkh; ga.Bl[1] = (const __nv_bfloat16*)pwkl;
    ga.Bh[2] = (const __nv_bfloat16*)pwvh; ga.Bl[2] = (const __nv_bfloat16*)pwvl;
    ga.Bh[3] = (const __nv_bfloat16*)pwoh; ga.Bl[3] = (const __nv_bfloat16*)pwol;
    ga.bias[0] = (const float*)pbeq; ga.bias[1] = (const float*)pbek;
    ga.bias[2] = (const float*)pbev; ga.bias[3] = Wo_b;
    ga.outF[0] = nullptr; ga.outF[1] = nullptr; ga.outF[2] = (float*)pV; ga.outF[3] = out;
    ga.outH[0] = (__nv_bfloat16*)pQph; ga.outL[0] = (__nv_bfloat16*)pQpl;
    ga.outH[1] = (__nv_bfloat16*)pKph; ga.outL[1] = (__nv_bfloat16*)pKpl;
    ga.outH[2] = nullptr; ga.outL[2] = nullptr;
    ga.outH[3] = nullptr; ga.outL[3] = nullptr;
    ga.loraKA = (const float*)pKA; ga.loraB = Bv_w;

    // ---- launches (launch #5 = fused QKV gemm, for ncu -s 5 -c 1) ----
    actconv_kernel<<<dim3((TOK*DMODEL/4)/256, 1, 3), 256>>>(aa);          // 0
    wprep_kernel<<<dim3(DMODEL/32, HDIM/32, 4), 256>>>(wa);               // 1
    beff_kernel<<<dim3(HDIM/256, 1, 3), 256>>>(ba);                       // 2
    ka_kernel<<<TOK/8, 256>>>(keys, Av_w, (float*)pKA);                   // 3
    zero_kernel<<<(BB*NH*SS)/256, 256>>>((float*)pcs);                    // 4

    gemm_mma<<<dim3(HDIM/128, TOK/128, 3), 256, GEMM_SMEM>>>(ga, 0);      // 5: QKV

    attn1_mma<<<dim3(136, BB*NH), 256, A1_SMEM>>>();                      // 6
    vrt_kernel<<<dim3(SS/32, 2, BB*NH), 256>>>();                         // 7
    attn2_mma<<<dim3(16, BB*NH), 256, A2_SMEM>>>();                       // 8

    gemm_mma<<<dim3(HDIM/128, TOK/128, 1), 256, GEMM_SMEM>>>(ga, 1);      // 9: O
}

// round 7
// speedup vs baseline: 2.3512x; 1.0292x over previous
#include <cuda_runtime.h>
#include <cuda_bf16.h>
#include <math.h>
#include <stdint.h>

#define BB     4
#define SS     2048
#define DMODEL 1024
#define NH     16
#define HD     64
#define HDIM   1024
#define RK     8
#define TOK    (BB*SS)   // 8192

// ------------------- device scratch (static; allocation-free) -------------------
__device__ float g_beq[HDIM];
__device__ float g_bek[HDIM];
__device__ float g_bev[HDIM];
__device__ float g_V[(size_t)TOK*HDIM];
__device__ float g_colsum[(size_t)BB*NH*SS];
__device__ float g_KA[(size_t)TOK*RK];

__device__ __nv_bfloat16 g_qh[(size_t)TOK*DMODEL], g_ql[(size_t)TOK*DMODEL];
__device__ __nv_bfloat16 g_kh[(size_t)TOK*DMODEL], g_kl[(size_t)TOK*DMODEL];
__device__ __nv_bfloat16 g_vh[(size_t)TOK*DMODEL], g_vl[(size_t)TOK*DMODEL];
__device__ __nv_bfloat16 g_Qph[(size_t)TOK*HDIM], g_Qpl[(size_t)TOK*HDIM];
__device__ __nv_bfloat16 g_Kph[(size_t)TOK*HDIM], g_Kpl[(size_t)TOK*HDIM];
__device__ __nv_bfloat16 g_aoh[(size_t)TOK*HDIM], g_aol[(size_t)TOK*HDIM];
__device__ __nv_bfloat16 g_Ehi[(size_t)BB*NH*SS*SS];
__device__ __nv_bfloat16 g_Elo[(size_t)BB*NH*SS*SS];
__device__ __nv_bfloat16 g_Vrth[(size_t)BB*NH*64*SS];
__device__ __nv_bfloat16 g_Vrtl[(size_t)BB*NH*64*SS];
__device__ __nv_bfloat16 g_wqh[DMODEL*HDIM], g_wql[DMODEL*HDIM];
__device__ __nv_bfloat16 g_wkh[DMODEL*HDIM], g_wkl[DMODEL*HDIM];
__device__ __nv_bfloat16 g_wvh[DMODEL*HDIM], g_wvl[DMODEL*HDIM];
__device__ __nv_bfloat16 g_woh[DMODEL*HDIM], g_wol[DMODEL*HDIM];

// ------------------- helpers ------------------------------------------------------
__device__ __forceinline__ uint32_t smem_u32(const void* p) {
    uint32_t a;
    asm("{ .reg .u64 t; cvta.to.shared.u64 t, %1; cvt.u32.u64 %0, t; }" : "=r"(a) : "l"(p));
    return a;
}
__device__ __forceinline__ void cpa16(uint32_t dst, const void* src) {
    asm volatile("cp.async.cg.shared.global [%0], [%1], 16;"
                 :: "r"(dst), "l"(__cvta_generic_to_global(src)));
}
#define CPA_COMMIT() asm volatile("cp.async.commit_group;")
#define CPA_WAIT1()  asm volatile("cp.async.wait_group 1;")
#define CPA_WAIT0()  asm volatile("cp.async.wait_group 0;")

#define LDSM4(r, a) \
    asm volatile("ldmatrix.sync.aligned.m8n8.x4.shared.b16 {%0,%1,%2,%3}, [%4];" \
        : "=r"((r)[0]), "=r"((r)[1]), "=r"((r)[2]), "=r"((r)[3]) : "r"(a))

#define MMA16816(c, a, b0, b1) \
    asm volatile("mma.sync.aligned.m16n8k16.row.col.f32.bf16.bf16.f32 " \
        "{%0,%1,%2,%3}, {%4,%5,%6,%7}, {%8,%9}, {%0,%1,%2,%3};" \
        : "+f"((c)[0]), "+f"((c)[1]), "+f"((c)[2]), "+f"((c)[3]) \
        : "r"((a)[0]), "r"((a)[1]), "r"((a)[2]), "r"((a)[3]), "r"(b0), "r"(b1))

// ------------------- fused prep kernels -------------------------------------------
struct ActArgs { const float* X[3]; __nv_bfloat16 *hi[3], *lo[3]; };
__global__ void actconv_kernel(ActArgs aa)
{
    int z = blockIdx.z;
    const float* X = aa.X[z];
    __nv_bfloat16* hi = aa.hi[z];
    __nv_bfloat16* lo = aa.lo[z];
    size_t i = ((size_t)blockIdx.x * 256 + threadIdx.x) * 4;
    float4 v = *(const float4*)&X[i];
    __nv_bfloat16 h0 = __float2bfloat16(v.x), h1 = __float2bfloat16(v.y);
    __nv_bfloat16 h2 = __float2bfloat16(v.z), h3 = __float2bfloat16(v.w);
    __nv_bfloat162 ph0 = {h0, h1}, ph1 = {h2, h3};
    __nv_bfloat162 pl0 = {__float2bfloat16(v.x - __bfloat162float(h0)),
                          __float2bfloat16(v.y - __bfloat162float(h1))};
    __nv_bfloat162 pl1 = {__float2bfloat16(v.z - __bfloat162float(h2)),
                          __float2bfloat16(v.w - __bfloat162float(h3))};
    *(__nv_bfloat162*)&hi[i]   = ph0;  *(__nv_bfloat162*)&hi[i+2] = ph1;
    *(__nv_bfloat162*)&lo[i]   = pl0;  *(__nv_bfloat162*)&lo[i+2] = pl1;
}

struct WprepArgs { const float *W[4], *A[4], *Bw[4]; __nv_bfloat16 *hi[4], *lo[4]; };
__global__ __launch_bounds__(256) void wprep_kernel(WprepArgs wa)
{
    __shared__ float t[32][33];
    int z = blockIdx.z;
    const float* W = wa.W[z];
    const float* A = wa.A[z];
    const float* Bw = wa.Bw[z];
    __nv_bfloat16* hi = wa.hi[z];
    __nv_bfloat16* lo = wa.lo[z];
    int kb = blockIdx.x * 32, nb = blockIdx.y * 32;
    int x = threadIdx.x & 31, y = threadIdx.x >> 5;
#pragma unroll
    for (int i = y; i < 32; i += 8) {
        int k = kb + i, n = nb + x;
        float v = W[(size_t)k*HDIM + n];
        if (A) {
#pragma unroll
            for (int r = 0; r < RK; r++) v += A[k*RK + r] * Bw[r*HDIM + n];
        }
        t[i][x] = v;
    }
    __syncthreads();
#pragma unroll
    for (int i = y; i < 32; i += 8) {
        int n = nb + i, k = kb + x;
        float v = t[x][i];
        __nv_bfloat16 h = __float2bfloat16(v);
        hi[(size_t)n*DMODEL + k] = h;
        lo[(size_t)n*DMODEL + k] = __float2bfloat16(v - __bfloat162float(h));
    }
}

struct BeffArgs { const float *Wb[3], *Ab[3], *Bw[3], *Bb[3]; float* out[3]; };
__global__ void beff_kernel(BeffArgs ba)
{
    int z = blockIdx.z;
    int j = blockIdx.x * 256 + threadIdx.x;
    float acc = ba.Wb[z][j] + ba.Bb[z][j];
    const float* Ab = ba.Ab[z];
    const float* Bw = ba.Bw[z];
#pragma unroll
    for (int r = 0; r < RK; r++) acc += Ab[r] * Bw[r*HDIM + j];
    ba.out[z][j] = acc;
}

__global__ void zero_kernel(float* p) { p[blockIdx.x * 256 + threadIdx.x] = 0.f; }

// KA[tok,8] = keys @ Av. Av cached in smem (transposed), float4 key loads.
// 8 warps/block, 4 rows per warp, grid = TOK/32 = 256.
__global__ __launch_bounds__(256) void ka_kernel(const float* __restrict__ keys,
                                                 const float* __restrict__ Av,
                                                 float* __restrict__ KA)
{
    __shared__ float avT[RK][DMODEL];   // 32 KB
    int tid = threadIdx.x;
    // load Av [1024][8] -> avT[8][1024] via float4
#pragma unroll
    for (int f = tid; f < DMODEL*RK/4; f += 256) {
        int k = f >> 1, j = (f & 1) * 4;
        float4 v = ((const float4*)Av)[f];
        avT[j+0][k] = v.x; avT[j+1][k] = v.y;
        avT[j+2][k] = v.z; avT[j+3][k] = v.w;
    }
    __syncthreads();

    int warp = tid >> 5, lane = tid & 31;
#pragma unroll
    for (int rr = 0; rr < 4; rr++) {
        int row = blockIdx.x * 32 + warp * 4 + rr;
        const float4* kr = (const float4*)(keys + (size_t)row * DMODEL);
        float acc[RK];
#pragma unroll
        for (int r = 0; r < RK; r++) acc[r] = 0.f;
#pragma unroll
        for (int i = 0; i < 8; i++) {
            int k4 = lane + i * 32;
            float4 kv = kr[k4];
            int k = 4 * k4;
#pragma unroll
            for (int r = 0; r < RK; r++) {
                float4 av = *(const float4*)&avT[r][k];
                acc[r] += kv.x*av.x + kv.y*av.y + kv.z*av.z + kv.w*av.w;
            }
        }
#pragma unroll
        for (int r = 0; r < RK; r++) {
#pragma unroll
            for (int off = 16; off > 0; off >>= 1)
                acc[r] += __shfl_down_sync(0xffffffffu, acc[r], off);
        }
        if (lane == 0) {
#pragma unroll
            for (int r = 0; r < RK; r++) KA[(size_t)row*RK + r] = acc[r];
        }
    }
}

// ------------------- fused mma.sync split-bf16 GEMM -------------------------------
static constexpr int STAGE_BYTES = 40960;
static constexpr int GEMM_SMEM   = 2 * STAGE_BYTES;

struct GemmArgs {
    const __nv_bfloat16 *Ah[4], *Al[4], *Bh[4], *Bl[4];
    const float* bias[4];
    float* outF[4];
    __nv_bfloat16 *outH[4], *outL[4];
    const float *loraKA, *loraB;
};

__global__ __launch_bounds__(256, 2)
void gemm_mma(GemmArgs ga, int op)
{
    extern __shared__ char smem[];
    const uint32_t sb = smem_u32(smem);
    const int z = op ? 3 : blockIdx.z;
    const __nv_bfloat16* Ah = ga.Ah[z];
    const __nv_bfloat16* Al = ga.Al[z];
    const __nv_bfloat16* Bh = ga.Bh[z];
    const __nv_bfloat16* Bl = ga.Bl[z];
    const float* bias = ga.bias[z];
    float* outF = ga.outF[z];
    __nv_bfloat16* outH = ga.outH[z];
    __nv_bfloat16* outL = ga.outL[z];
    const float* loraKA = (z == 2) ? ga.loraKA : nullptr;
    const float* loraB  = ga.loraB;

    const int tid  = threadIdx.x;
    const int lane = tid & 31;
    const int warp = tid >> 5;
    const int wm = warp >> 2, wn = warp & 3;
    const int m0 = blockIdx.y * 128, n0 = blockIdx.x * 128;

    float acc[4][4][4];
#pragma unroll
    for (int i = 0; i < 4; i++)
#pragma unroll
        for (int j = 0; j < 4; j++)
#pragma unroll
            for (int k = 0; k < 4; k++) acc[i][j][k] = 0.f;

    auto load_stage = [&](int st, int chunk) {
        int k0 = chunk * 32;
        const __nv_bfloat16* tp[4] = {Ah, Al, Bh, Bl};
        uint32_t sbase = sb + st * STAGE_BYTES;
#pragma unroll
        for (int i = 0; i < 8; i++) {
            const int t = i >> 1;
            int j = (i & 1) ? tid + 256 : tid;
            int row = j >> 2, sg = j & 3;
            int r0 = (t < 2) ? m0 : n0;
            cpa16(sbase + t * 10240 + row * 80 + sg * 16,
                  tp[t] + (size_t)(r0 + row) * 1024 + k0 + sg * 8);
        }
    };

    auto compute_stage = [&](int st) {
        uint32_t ab = sb + st * STAGE_BYTES;
#pragma unroll
        for (int kk = 0; kk < 2; kk++) {
            uint32_t ahr[4][4], alr[4][4], bh2[4][2], bl2[4][2];
            uint32_t aoff = (uint32_t)(wm*64 + (lane & 15)) * 80
                          + (uint32_t)(kk*16 + (lane >> 4) * 8) * 2;
#pragma unroll
            for (int mt = 0; mt < 4; mt++) {
                LDSM4(ahr[mt], ab + aoff + mt * (16*80));
                LDSM4(alr[mt], ab + 10240 + aoff + mt * (16*80));
            }
            uint32_t boff = (uint32_t)(wn*32 + (lane & 7) + ((lane >> 4) << 3)) * 80
                          + (uint32_t)(kk*16 + ((lane >> 3) & 1) * 8) * 2;
            {
                uint32_t t0[4], t1[4];
                LDSM4(t0, ab + 20480 + boff);
                LDSM4(t1, ab + 20480 + boff + 16*80);
                bh2[0][0]=t0[0]; bh2[0][1]=t0[1]; bh2[1][0]=t0[2]; bh2[1][1]=t0[3];
                bh2[2][0]=t1[0]; bh2[2][1]=t1[1]; bh2[3][0]=t1[2]; bh2[3][1]=t1[3];
                LDSM4(t0, ab + 30720 + boff);
                LDSM4(t1, ab + 30720 + boff + 16*80);
                bl2[0][0]=t0[0]; bl2[0][1]=t0[1]; bl2[1][0]=t0[2]; bl2[1][1]=t0[3];
                bl2[2][0]=t1[0]; bl2[2][1]=t1[1]; bl2[3][0]=t1[2]; bl2[3][1]=t1[3];
            }
#pragma unroll
            for (int mt = 0; mt < 4; mt++)
#pragma unroll
                for (int nt = 0; nt < 4; nt++) {
                    MMA16816(acc[mt][nt], ahr[mt], bh2[nt][0], bh2[nt][1]);
                    MMA16816(acc[mt][nt], ahr[mt], bl2[nt][0], bl2[nt][1]);
                    MMA16816(acc[mt][nt], alr[mt], bh2[nt][0], bh2[nt][1]);
                }
        }
    };

    load_stage(0, 0);
    CPA_COMMIT();
    load_stage(1, 1);
    CPA_COMMIT();

#pragma unroll 1
    for (int c = 0; c < 32; c++) {
        CPA_WAIT1();
        __syncthreads();
        compute_stage(c & 1);
        __syncthreads();
        if (c + 2 < 32) load_stage(c & 1, c + 2);
        CPA_COMMIT();
    }

    int r_ = lane >> 2, c_ = (lane & 3) * 2;
#pragma unroll
    for (int mt = 0; mt < 4; mt++) {
        int row = m0 + wm*64 + mt*16 + r_;
        float ka0[RK], ka1[RK];
        if (loraKA) {
#pragma unroll
            for (int r = 0; r < RK; r++) {
                ka0[r] = loraKA[(size_t)row*RK + r];
                ka1[r] = loraKA[(size_t)(row+8)*RK + r];
            }
        }
#pragma unroll
        for (int nt = 0; nt < 4; nt++) {
            int col = n0 + wn*32 + nt*8 + c_;
            float b0 = bias[col], b1 = bias[col + 1];
            float v00 = acc[mt][nt][0] + b0, v01 = acc[mt][nt][1] + b1;
            float v10 = acc[mt][nt][2] + b0, v11 = acc[mt][nt][3] + b1;
            if (loraKA) {
#pragma unroll
                for (int r = 0; r < RK; r++) {
                    float w0 = loraB[r*HDIM + col], w1 = loraB[r*HDIM + col + 1];
                    v00 += ka0[r] * w0;  v01 += ka0[r] * w1;
                    v10 += ka1[r] * w0;  v11 += ka1[r] * w1;
                }
            }
            if (outF) {
                *(float2*)&outF[(size_t)row * 1024 + col] = {v00, v01};
                *(float2*)&outF[(size_t)(row + 8) * 1024 + col] = {v10, v11};
            } else {
                __nv_bfloat16 h00 = __float2bfloat16(v00), h01 = __float2bfloat16(v01);
                __nv_bfloat16 h10 = __float2bfloat16(v10), h11 = __float2bfloat16(v11);
                __nv_bfloat162 hp0 = {h00, h01}, hp1 = {h10, h11};
                __nv_bfloat162 lp0 = {__float2bfloat16(v00 - __bfloat162float(h00)),
                                      __float2bfloat16(v01 - __bfloat162float(h01))};
                __nv_bfloat162 lp1 = {__float2bfloat16(v10 - __bfloat162float(h10)),
                                      __float2bfloat16(v11 - __bfloat162float(h11))};
                *(__nv_bfloat162*)&outH[(size_t)row * 1024 + col] = hp0;
                *(__nv_bfloat162*)&outH[(size_t)(row + 8) * 1024 + col] = hp1;
                *(__nv_bfloat162*)&outL[(size_t)row * 1024 + col] = lp0;
                *(__nv_bfloat162*)&outL[(size_t)(row + 8) * 1024 + col] = lp1;
            }
        }
    }
}

// ------------------- pass 1 (mma): E = exp(QK^T) masked, column sums -------------
static constexpr int A1_PITCH = 144;
static constexpr int A1_TILE  = 128 * A1_PITCH;
static constexpr int A1_SMEM  = 4 * A1_TILE;

__global__ __launch_bounds__(256, 2) void attn1_mma()
{
    extern __shared__ char smem[];
    int idx = blockIdx.x;
    int qt = (int)((sqrtf(8.f*idx + 1.f) - 1.f) * 0.5f);
    if ((qt+1)*(qt+2)/2 <= idx) qt++;
    if (qt*(qt+1)/2 > idx) qt--;
    int kt = idx - qt*(qt+1)/2;
    int bh = blockIdx.y;
    const uint32_t sb = smem_u32(smem);
    int b = bh >> 4, h = bh & 15;
    int q0 = qt * 128, k0 = kt * 128;
    int tid = threadIdx.x, lane = tid & 31, warp = tid >> 5;
    int wm = warp >> 2, wn = warp & 3;

    {
        const __nv_bfloat16* tp[4] = {g_Qph, g_Qpl, g_Kph, g_Kpl};
#pragma unroll
        for (int t = 0; t < 4; t++) {
            int r0 = (t < 2) ? q0 : k0;
#pragma unroll
            for (int i = 0; i < 4; i++) {
                int ix = tid + i * 256;
                int row = ix >> 3, sg = ix & 7;
                cpa16(sb + t * A1_TILE + row * A1_PITCH + sg * 16,
                      tp[t] + (size_t)(b*SS + r0 + row) * 1024 + h*64 + sg * 8);
            }
        }
    }
    CPA_COMMIT(); CPA_WAIT0();
    __syncthreads();

    float acc[4][4][4];
#pragma unroll
    for (int i = 0; i < 4; i++)
#pragma unroll
        for (int j = 0; j < 4; j++)
#pragma unroll
            for (int k = 0; k < 4; k++) acc[i][j][k] = 0.f;

#pragma unroll
    for (int kk = 0; kk < 4; kk++) {
        uint32_t ahr[4][4], alr[4][4], bhf[4][2], blf[4][2];
        uint32_t aoff = (uint32_t)(wm*64 + (lane & 15)) * A1_PITCH
                      + (uint32_t)(kk*16 + (lane >> 4) * 8) * 2;
#pragma unroll
        for (int mt = 0; mt < 4; mt++) {
            LDSM4(ahr[mt], sb + aoff + mt * (16*A1_PITCH));
            LDSM4(alr[mt], sb + A1_TILE + aoff + mt * (16*A1_PITCH));
        }
        uint32_t boff = (uint32_t)(wn*32 + (lane & 7) + ((lane >> 4) << 3)) * A1_PITCH
                      + (uint32_t)(kk*16 + ((lane >> 3) & 1) * 8) * 2;
        {
            uint32_t t0[4], t1[4];
            LDSM4(t0, sb + 2*A1_TILE + boff);
            LDSM4(t1, sb + 2*A1_TILE + boff + 16*A1_PITCH);
            bhf[0][0]=t0[0]; bhf[0][1]=t0[1]; bhf[1][0]=t0[2]; bhf[1][1]=t0[3];
            bhf[2][0]=t1[0]; bhf[2][1]=t1[1]; bhf[3][0]=t1[2]; bhf[3][1]=t1[3];
            LDSM4(t0, sb + 3*A1_TILE + boff);
            LDSM4(t1, sb + 3*A1_TILE + boff + 16*A1_PITCH);
            blf[0][0]=t0[0]; blf[0][1]=t0[1]; blf[1][0]=t0[2]; blf[1][1]=t0[3];
            blf[2][0]=t1[0]; blf[2][1]=t1[1]; blf[3][0]=t1[2]; blf[3][1]=t1[3];
        }
#pragma unroll
        for (int mt = 0; mt < 4; mt++)
#pragma unroll
            for (int nt = 0; nt < 4; nt++) {
                MMA16816(acc[mt][nt], ahr[mt], bhf[nt][0], bhf[nt][1]);
                MMA16816(acc[mt][nt], ahr[mt], blf[nt][0], blf[nt][1]);
                MMA16816(acc[mt][nt], alr[mt], bhf[nt][0], bhf[nt][1]);
            }
    }

    __syncthreads();
    float* cs = (float*)smem;
    if (tid < 128) cs[tid] = 0.f;
    __syncthreads();

    const bool diag = (qt == kt);
    int r_ = lane >> 2, c_ = (lane & 3) * 2;
    float cs0[4] = {0,0,0,0}, cs1[4] = {0,0,0,0};
#pragma unroll
    for (int mt = 0; mt < 4; mt++) {
        int qb = q0 + wm*64 + mt*16;
#pragma unroll
        for (int nt = 0; nt < 4; nt++) {
            int k = k0 + wn*32 + nt*8 + c_;
            float e00 = __expf(acc[mt][nt][0]);
            float e01 = __expf(acc[mt][nt][1]);
            float e10 = __expf(acc[mt][nt][2]);
            float e11 = __expf(acc[mt][nt][3]);
            int qr0 = qb + r_, qr1 = qb + r_ + 8;
            if (diag) {
                if (qr0 < k)     e00 = 0.f;
                if (qr0 < k + 1) e01 = 0.f;
                if (qr1 < k)     e10 = 0.f;
                if (qr1 < k + 1) e11 = 0.f;
            }
            cs0[nt] += e00 + e10;
            cs1[nt] += e01 + e11;
            __nv_bfloat16 h00 = __float2bfloat16(e00), h01 = __float2bfloat16(e01);
            __nv_bfloat16 h10 = __float2bfloat16(e10), h11 = __float2bfloat16(e11);
            __nv_bfloat162 hp0 = {h00, h01}, hp1 = {h10, h11};
            __nv_bfloat162 lp0 = {__float2bfloat16(e00 - __bfloat162float(h00)),
                                  __float2bfloat16(e01 - __bfloat162float(h01))};
            __nv_bfloat162 lp1 = {__float2bfloat16(e10 - __bfloat162float(h10)),
                                  __float2bfloat16(e11 - __bfloat162float(h11))};
            size_t b0i = ((size_t)bh*SS + qr0) * SS + k;
            size_t b1i = ((size_t)bh*SS + qr1) * SS + k;
            *(__nv_bfloat162*)&g_Ehi[b0i] = hp0;  *(__nv_bfloat162*)&g_Elo[b0i] = lp0;
            *(__nv_bfloat162*)&g_Ehi[b1i] = hp1;  *(__nv_bfloat162*)&g_Elo[b1i] = lp1;
        }
    }
#pragma unroll
    for (int nt = 0; nt < 4; nt++) {
        atomicAdd(&cs[wn*32 + nt*8 + c_],     cs0[nt]);
        atomicAdd(&cs[wn*32 + nt*8 + c_ + 1], cs1[nt]);
    }
    __syncthreads();
    if (tid < 128)
        atomicAdd(&g_colsum[(size_t)bh*SS + k0 + tid], cs[tid]);
}

// ------------------- Vrt prep ------------------------------------------------------
__global__ __launch_bounds__(256) void vrt_kernel()
{
    __shared__ float t[32][33];
    int kt = blockIdx.x, dt = blockIdx.y, bh = blockIdx.z;
    int b = bh >> 4, h = bh & 15;
    int k0 = kt * 32, d0 = dt * 32;
    int x = threadIdx.x & 31, y = threadIdx.x >> 5;
#pragma unroll
    for (int i = y; i < 32; i += 8) {
        int k = k0 + i;
        float r = 1.0f / (g_colsum[(size_t)bh*SS + k] * 8.0f);
        t[i][x] = g_V[(size_t)(b*SS + k) * HDIM + h*64 + d0 + x] * r;
    }
    __syncthreads();
#pragma unroll
    for (int i = y; i < 32; i += 8) {
        int d = d0 + i, k = k0 + x;
        float v = t[x][i];
        __nv_bfloat16 hh = __float2bfloat16(v);
        size_t idx = ((size_t)bh*64 + d) * SS + k;
        g_Vrth[idx] = hh;
        g_Vrtl[idx] = __float2bfloat16(v - __bfloat162float(hh));
    }
}

// ------------------- pass 2 (mma): attO = E @ Vrt^T, 3-stage, 1 sync, LPT --------
static constexpr int A2_PITCH = 80;
static constexpr int A2_ATILE = 128 * A2_PITCH;
static constexpr int A2_BTILE = 64 * A2_PITCH;
static constexpr int A2_STAGE = 2*A2_ATILE + 2*A2_BTILE;   // 30720
static constexpr int A2_SMEM  = 3 * A2_STAGE;              // 92160

__global__ __launch_bounds__(256, 2) void attn2_mma()
{
    extern __shared__ char smem[];
    const uint32_t sb = smem_u32(smem);
    int qt = (int)gridDim.x - 1 - (int)blockIdx.x;    // LPT: heavy tiles first
    int bh = blockIdx.y;
    int b = bh >> 4, h = bh & 15;
    int q0 = qt * 128;
    int tid = threadIdx.x, lane = tid & 31, warp = tid >> 5;
    int wm = warp >> 1, wn = warp & 1;
    int nch = (qt + 1) * 4;

    float acc[2][4][4];
#pragma unroll
    for (int i = 0; i < 2; i++)
#pragma unroll
        for (int j = 0; j < 4; j++)
#pragma unroll
            for (int k = 0; k < 4; k++) acc[i][j][k] = 0.f;

    auto load_stage = [&](int st, int c) {
        int k0 = c * 32;
        uint32_t sbase = sb + st * A2_STAGE;
#pragma unroll
        for (int i = 0; i < 2; i++) {
            int ix = tid + i * 256;
            int row = ix >> 2, sg = ix & 3;
            size_t gi = ((size_t)bh*SS + q0 + row) * SS + k0 + sg * 8;
            cpa16(sbase + row * A2_PITCH + sg * 16, &g_Ehi[gi]);
            cpa16(sbase + A2_ATILE + row * A2_PITCH + sg * 16, &g_Elo[gi]);
        }
        {
            int row = tid >> 2, sg = tid & 3;
            size_t gi = ((size_t)bh*64 + row) * SS + k0 + sg * 8;
            cpa16(sbase + 2*A2_ATILE + row * A2_PITCH + sg * 16, &g_Vrth[gi]);
            cpa16(sbase + 2*A2_ATILE + A2_BTILE + row * A2_PITCH + sg * 16, &g_Vrtl[gi]);
        }
    };

    auto compute_stage = [&](int st) {
        uint32_t ab = sb + st * A2_STAGE;
#pragma unroll
        for (int kk = 0; kk < 2; kk++) {
            uint32_t ahr[2][4], alr[2][4], bhf[4][2], blf[4][2];
            uint32_t aoff = (uint32_t)(wm*32 + (lane & 15)) * A2_PITCH
                          + (uint32_t)(kk*16 + (lane >> 4) * 8) * 2;
#pragma unroll
            for (int mt = 0; mt < 2; mt++) {
                LDSM4(ahr[mt], ab + aoff + mt * (16*A2_PITCH));
                LDSM4(alr[mt], ab + A2_ATILE + aoff + mt * (16*A2_PITCH));
            }
            uint32_t boff = (uint32_t)(wn*32 + (lane & 7) + ((lane >> 4) << 3)) * A2_PITCH
                          + (uint32_t)(kk*16 + ((lane >> 3) & 1) * 8) * 2;
            {
                uint32_t t0[4], t1[4];
                LDSM4(t0, ab + 2*A2_ATILE + boff);
                LDSM4(t1, ab + 2*A2_ATILE + boff + 16*A2_PITCH);
                bhf[0][0]=t0[0]; bhf[0][1]=t0[1]; bhf[1][0]=t0[2]; bhf[1][1]=t0[3];
                bhf[2][0]=t1[0]; bhf[2][1]=t1[1]; bhf[3][0]=t1[2]; bhf[3][1]=t1[3];
                LDSM4(t0, ab + 2*A2_ATILE + A2_BTILE + boff);
                LDSM4(t1, ab + 2*A2_ATILE + A2_BTILE + boff + 16*A2_PITCH);
                blf[0][0]=t0[0]; blf[0][1]=t0[1]; blf[1][0]=t0[2]; blf[1][1]=t0[3];
                blf[2][0]=t1[0]; blf[2][1]=t1[1]; blf[3][0]=t1[2]; blf[3][1]=t1[3];
            }
#pragma unroll
            for (int mt = 0; mt < 2; mt++)
#pragma unroll
                for (int nt = 0; nt < 4; nt++) {
                    MMA16816(acc[mt][nt], ahr[mt], bhf[nt][0], bhf[nt][1]);
                    MMA16816(acc[mt][nt], ahr[mt], blf[nt][0], blf[nt][1]);
                    MMA16816(acc[mt][nt], alr[mt], bhf[nt][0], bhf[nt][1]);
                }
        }
    };

    load_stage(0, 0);
    CPA_COMMIT();
    load_stage(1, 1);
    CPA_COMMIT();

    // single __syncthreads per chunk: buffer (c+2)%3 was consumed at iter c-1,
    // and this iteration's sync orders all its readers before the new cp.async.
    for (int c = 0; c < nch; c++) {
        CPA_WAIT1();
        __syncthreads();
        if (c + 2 < nch) load_stage((c + 2) % 3, c + 2);
        CPA_COMMIT();
        compute_stage(c % 3);
    }

    int r_ = lane >> 2, c_ = (lane & 3) * 2;
#pragma unroll
    for (int mt = 0; mt < 2; mt++)
#pragma unroll
        for (int nt = 0; nt < 4; nt++) {
            int q  = q0 + wm*32 + mt*16 + r_;
            int d  = wn*32 + nt*8 + c_;
            float v00 = acc[mt][nt][0], v01 = acc[mt][nt][1];
            float v10 = acc[mt][nt][2], v11 = acc[mt][nt][3];
            size_t i0 = (size_t)(b*SS + q) * HDIM + h*64 + d;
            size_t i1 = (size_t)(b*SS + q + 8) * HDIM + h*64 + d;
            __nv_bfloat16 h00 = __float2bfloat16(v00), h01 = __float2bfloat16(v01);
            __nv_bfloat16 h10 = __float2bfloat16(v10), h11 = __float2bfloat16(v11);
            __nv_bfloat162 hp0 = {h00, h01}, hp1 = {h10, h11};
            __nv_bfloat162 lp0 = {__float2bfloat16(v00 - __bfloat162float(h00)),
                                  __float2bfloat16(v01 - __bfloat162float(h01))};
            __nv_bfloat162 lp1 = {__float2bfloat16(v10 - __bfloat162float(h10)),
                                  __float2bfloat16(v11 - __bfloat162float(h11))};
            *(__nv_bfloat162*)&g_aoh[i0] = hp0;  *(__nv_bfloat162*)&g_aol[i0] = lp0;
            *(__nv_bfloat162*)&g_aoh[i1] = hp1;  *(__nv_bfloat162*)&g_aol[i1] = lp1;
        }
}

// ------------------- launch ------------------------------------------------------
extern "C" void kernel_launch(void* const* d_in, const int* in_sizes, int n_in,
                              void* d_out, int out_size)
{
    const float* queries = (const float*)d_in[0];
    const float* keys    = (const float*)d_in[1];
    const float* values  = (const float*)d_in[2];
    const float* Wq_w = (const float*)d_in[3];  const float* Wq_b = (const float*)d_in[4];
    const float* Wk_w = (const float*)d_in[5];  const float* Wk_b = (const float*)d_in[6];
    const float* Wv_w = (const float*)d_in[7];  const float* Wv_b = (const float*)d_in[8];
    const float* Aq_w = (const float*)d_in[9];  const float* Aq_b = (const float*)d_in[10];
    const float* Bq_w = (const float*)d_in[11]; const float* Bq_b = (const float*)d_in[12];
    const float* Ak_w = (const float*)d_in[13]; const float* Ak_b = (const float*)d_in[14];
    const float* Bk_w = (const float*)d_in[15]; const float* Bk_b = (const float*)d_in[16];
    const float* Av_w = (const float*)d_in[17]; const float* Av_b = (const float*)d_in[18];
    const float* Bv_w = (const float*)d_in[19]; const float* Bv_b = (const float*)d_in[20];
    const float* Wo_w = (const float*)d_in[21]; const float* Wo_b = (const float*)d_in[22];
    float* out = (float*)d_out;

    cudaFuncSetAttribute(gemm_mma, cudaFuncAttributeMaxDynamicSharedMemorySize, GEMM_SMEM);
    cudaFuncSetAttribute(attn1_mma, cudaFuncAttributeMaxDynamicSharedMemorySize, A1_SMEM);
    cudaFuncSetAttribute(attn2_mma, cudaFuncAttributeMaxDynamicSharedMemorySize, A2_SMEM);

    void *pbeq, *pbek, *pbev, *pV, *pcs, *pKA;
    void *pqh, *pql, *pkh, *pkl, *pvh, *pvl, *paoh, *paol;
    void *pQph, *pQpl, *pKph, *pKpl;
    void *pwqh, *pwql, *pwkh, *pwkl, *pwvh, *pwvl, *pwoh, *pwol;
    cudaGetSymbolAddress(&pbeq, g_beq); cudaGetSymbolAddress(&pbek, g_bek);
    cudaGetSymbolAddress(&pbev, g_bev); cudaGetSymbolAddress(&pV, g_V);
    cudaGetSymbolAddress(&pcs, g_colsum); cudaGetSymbolAddress(&pKA, g_KA);
    cudaGetSymbolAddress(&pqh, g_qh); cudaGetSymbolAddress(&pql, g_ql);
    cudaGetSymbolAddress(&pkh, g_kh); cudaGetSymbolAddress(&pkl, g_kl);
    cudaGetSymbolAddress(&pvh, g_vh); cudaGetSymbolAddress(&pvl, g_vl);
    cudaGetSymbolAddress(&paoh, g_aoh); cudaGetSymbolAddress(&paol, g_aol);
    cudaGetSymbolAddress(&pQph, g_Qph); cudaGetSymbolAddress(&pQpl, g_Qpl);
    cudaGetSymbolAddress(&pKph, g_Kph); cudaGetSymbolAddress(&pKpl, g_Kpl);
    cudaGetSymbolAddress(&pwqh, g_wqh); cudaGetSymbolAddress(&pwql, g_wql);
    cudaGetSymbolAddress(&pwkh, g_wkh); cudaGetSymbolAddress(&pwkl, g_wkl);
    cudaGetSymbolAddress(&pwvh, g_wvh); cudaGetSymbolAddress(&pwvl, g_wvl);
    cudaGetSymbolAddress(&pwoh, g_woh); cudaGetSymbolAddress(&pwol, g_wol);

    ActArgs aa;
    aa.X[0] = queries; aa.X[1] = keys; aa.X[2] = values;
    aa.hi[0] = (__nv_bfloat16*)pqh; aa.hi[1] = (__nv_bfloat16*)pkh; aa.hi[2] = (__nv_bfloat16*)pvh;
    aa.lo[0] = (__nv_bfloat16*)pql; aa.lo[1] = (__nv_bfloat16*)pkl; aa.lo[2] = (__nv_bfloat16*)pvl;

    WprepArgs wa;
    wa.W[0] = Wq_w; wa.W[1] = Wk_w; wa.W[2] = Wv_w; wa.W[3] = Wo_w;
    wa.A[0] = Aq_w; wa.A[1] = Ak_w; wa.A[2] = nullptr; wa.A[3] = nullptr;
    wa.Bw[0] = Bq_w; wa.Bw[1] = Bk_w; wa.Bw[2] = nullptr; wa.Bw[3] = nullptr;
    wa.hi[0] = (__nv_bfloat16*)pwqh; wa.hi[1] = (__nv_bfloat16*)pwkh;
    wa.hi[2] = (__nv_bfloat16*)pwvh; wa.hi[3] = (__nv_bfloat16*)pwoh;
    wa.lo[0] = (__nv_bfloat16*)pwql; wa.lo[1] = (__nv_bfloat16*)pwkl;
    wa.lo[2] = (__nv_bfloat16*)pwvl; wa.lo[3] = (__nv_bfloat16*)pwol;

    BeffArgs ba;
    ba.Wb[0] = Wq_b; ba.Wb[1] = Wk_b; ba.Wb[2] = Wv_b;
    ba.Ab[0] = Aq_b; ba.Ab[1] = Ak_b; ba.Ab[2] = Av_b;
    ba.Bw[0] = Bq_w; ba.Bw[1] = Bk_w; ba.Bw[2] = Bv_w;
    ba.Bb[0] = Bq_b; ba.Bb[1] = Bk_b; ba.Bb[2] = Bv_b;
    ba.out[0] = (float*)pbeq; ba.out[1] = (float*)pbek; ba.out[2] = (float*)pbev;

    GemmArgs ga;
    ga.Ah[0] = (const __nv_bfloat16*)pqh;  ga.Al[0] = (const __nv_bfloat16*)pql;
    ga.Ah[1] = (const __nv_bfloat16*)pkh;  ga.Al[1] = (const __nv_bfloat16*)pkl;
    ga.Ah[2] = (const __nv_bfloat16*)pvh;  ga.Al[2] = (const __nv_bfloat16*)pvl;
    ga.Ah[3] = (const __nv_bfloat16*)paoh; ga.Al[3] = (const __nv_bfloat16*)paol;
    ga.Bh[0] = (const __nv_bfloat16*)pwqh; ga.Bl[0] = (const __nv_bfloat16*)pwql;
    ga.Bh[1] = (const __nv_bfloat16*)pwkh; ga.Bl[1] = (const __nv_bfloat16*)pwkl;
    ga.Bh[2] = (const __nv_bfloat16*)pwvh; ga.Bl[2] = (const __nv_bfloat16*)pwvl;
    ga.Bh[3] = (const __nv_bfloat16*)pwoh; ga.Bl[3] = (const __nv_bfloat16*)pwol;
    ga.bias[0] = (const float*)pbeq; ga.bias[1] = (const float*)pbek;
    ga.bias[2] = (const float*)pbev; ga.bias[3] = Wo_b;
    ga.outF[0] = nullptr; ga.outF[1] = nullptr; ga.outF[2] = (float*)pV; ga.outF[3] = out;
    ga.outH[0] = (__nv_bfloat16*)pQph; ga.outL[0] = (__nv_bfloat16*)pQpl;
    ga.outH[1] = (__nv_bfloat16*)pKph; ga.outL[1] = (__nv_bfloat16*)pKpl;
    ga.outH[2] = nullptr; ga.outL[2] = nullptr;
    ga.outH[3] = nullptr; ga.outL[3] = nullptr;
    ga.loraKA = (const float*)pKA; ga.loraB = Bv_w;

    actconv_kernel<<<dim3((TOK*DMODEL/4)/256, 1, 3), 256>>>(aa);
    wprep_kernel<<<dim3(DMODEL/32, HDIM/32, 4), 256>>>(wa);
    beff_kernel<<<dim3(HDIM/256, 1, 3), 256>>>(ba);
    ka_kernel<<<TOK/32, 256>>>(keys, Av_w, (float*)pKA);
    zero_kernel<<<(BB*NH*SS)/256, 256>>>((float*)pcs);

    gemm_mma<<<dim3(HDIM/128, TOK/128, 3), 256, GEMM_SMEM>>>(ga, 0);   // QKV

    attn1_mma<<<dim3(136, BB*NH), 256, A1_SMEM>>>();
    vrt_kernel<<<dim3(SS/32, 2, BB*NH), 256>>>();
    attn2_mma<<<dim3(16, BB*NH), 256, A2_SMEM>>>();

    gemm_mma<<<dim3(HDIM/128, TOK/128, 1), 256, GEMM_SMEM>>>(ga, 1);   // O
}